// round 1
// baseline (speedup 1.0000x reference)
#include <cuda_runtime.h>
#include <math.h>
#include <stdint.h>

// ---------------------------------------------------------------------------
// Problem constants
// ---------------------------------------------------------------------------
#define BATCH   64
#define SEQ     577
#define MTOK    (BATCH * SEQ)      // 36928 token rows
#define C_EMB   768
#define C_QKV   2304               // 3 * C_EMB
#define C_HID   3072
#define NHEAD   12
#define HDIM    64

// ---------------------------------------------------------------------------
// Scratch (device globals; no allocation allowed in kernel_launch)
// ---------------------------------------------------------------------------
__device__ float g_h  [(size_t)MTOK * C_EMB];   // LN output (reused for ln1 & ln2)
__device__ float g_qkv[(size_t)MTOK * C_QKV];   // qkv projection
__device__ float g_att[(size_t)MTOK * C_EMB];   // attention output (B,N,H,D)
__device__ float g_x1 [(size_t)MTOK * C_EMB];   // x + attn proj (residual 1)
__device__ float g_ff [(size_t)MTOK * C_HID];   // gelu(fc1) output

// ---------------------------------------------------------------------------
// LayerNorm: one block (256 threads) per row of 768
// ---------------------------------------------------------------------------
__global__ __launch_bounds__(256) void ln_ker(const float* __restrict__ x,
                                              const float* __restrict__ gamma,
                                              const float* __restrict__ beta,
                                              float* __restrict__ o)
{
    const int row = blockIdx.x;
    const float* xr = x + (size_t)row * C_EMB;
    float s = 0.f, s2 = 0.f;
    #pragma unroll
    for (int c = threadIdx.x; c < C_EMB; c += 256) {
        float v = xr[c];
        s += v; s2 += v * v;
    }
    // warp reduce
    #pragma unroll
    for (int off = 16; off > 0; off >>= 1) {
        s  += __shfl_down_sync(0xFFFFFFFFu, s,  off);
        s2 += __shfl_down_sync(0xFFFFFFFFu, s2, off);
    }
    __shared__ float shs[8], shs2[8];
    const int lane = threadIdx.x & 31, warp = threadIdx.x >> 5;
    if (lane == 0) { shs[warp] = s; shs2[warp] = s2; }
    __syncthreads();
    if (threadIdx.x == 0) {
        float ts = 0.f, ts2 = 0.f;
        #pragma unroll
        for (int w = 0; w < 8; w++) { ts += shs[w]; ts2 += shs2[w]; }
        float mean = ts * (1.0f / C_EMB);
        float var  = ts2 * (1.0f / C_EMB) - mean * mean;
        shs[0]  = mean;
        shs2[0] = rsqrtf(var + 1e-5f);
    }
    __syncthreads();
    const float mean = shs[0], rstd = shs2[0];
    float* orow = o + (size_t)row * C_EMB;
    #pragma unroll
    for (int c = threadIdx.x; c < C_EMB; c += 256)
        orow[c] = (xr[c] - mean) * rstd * gamma[c] + beta[c];
}

// ---------------------------------------------------------------------------
// SGEMM: C[M,N] = A[M,K] @ B[K,N] (+bias)(+residual)(+GELU)
// 128x128 tile, BK=8, 256 threads, 8x8 per-thread register tile.
// N must be divisible by 128, K by 8 (holds for all four GEMMs here).
// ---------------------------------------------------------------------------
#define EPI_NONE      0
#define EPI_BIAS_RES  1
#define EPI_BIAS_GELU 2

template<int EPI>
__global__ __launch_bounds__(256) void sgemm_ker(const float* __restrict__ A,
                                                 const float* __restrict__ B,
                                                 const float* __restrict__ bias,
                                                 const float* __restrict__ res,
                                                 float* __restrict__ C,
                                                 int M, int N, int K)
{
    __shared__ float As[8][128];   // As[k][m]
    __shared__ float Bs[8][128];   // Bs[k][n]

    const int bm = blockIdx.y * 128;
    const int bn = blockIdx.x * 128;
    const int t  = threadIdx.x;

    const int ar   = t >> 1;          // 0..127
    const int ac   = (t & 1) << 2;    // 0 or 4
    const int br   = t >> 5;          // 0..7
    const int bc   = (t & 31) << 2;   // 0..124

    const int ty = t >> 4;            // 0..15
    const int tx = t & 15;            // 0..15

    float acc[8][8];
    #pragma unroll
    for (int i = 0; i < 8; i++)
        #pragma unroll
        for (int j = 0; j < 8; j++) acc[i][j] = 0.f;

    for (int k0 = 0; k0 < K; k0 += 8) {
        // load A tile (128 x 8), transposed into As[k][m]
        const int arow = bm + ar;
        float4 av = make_float4(0.f, 0.f, 0.f, 0.f);
        if (arow < M)
            av = *(const float4*)(A + (size_t)arow * K + k0 + ac);
        As[ac + 0][ar] = av.x;
        As[ac + 1][ar] = av.y;
        As[ac + 2][ar] = av.z;
        As[ac + 3][ar] = av.w;
        // load B tile (8 x 128)
        float4 bv = *(const float4*)(B + (size_t)(k0 + br) * N + bn + bc);
        *(float4*)&Bs[br][bc] = bv;
        __syncthreads();

        #pragma unroll
        for (int kk = 0; kk < 8; kk++) {
            float a[8], b[8];
            *(float4*)&a[0] = *(float4*)&As[kk][ty * 8];
            *(float4*)&a[4] = *(float4*)&As[kk][ty * 8 + 4];
            *(float4*)&b[0] = *(float4*)&Bs[kk][tx * 8];
            *(float4*)&b[4] = *(float4*)&Bs[kk][tx * 8 + 4];
            #pragma unroll
            for (int i = 0; i < 8; i++)
                #pragma unroll
                for (int j = 0; j < 8; j++)
                    acc[i][j] += a[i] * b[j];
        }
        __syncthreads();
    }

    #pragma unroll
    for (int i = 0; i < 8; i++) {
        const int row = bm + ty * 8 + i;
        if (row >= M) continue;
        #pragma unroll
        for (int j = 0; j < 8; j++) {
            const int col = bn + tx * 8 + j;
            float v = acc[i][j];
            if (EPI != EPI_NONE) v += bias[col];
            if (EPI == EPI_BIAS_GELU)
                v = 0.5f * v * (1.0f + erff(v * 0.70710678118654752f));
            if (EPI == EPI_BIAS_RES)
                v += res[(size_t)row * N + col];
            C[(size_t)row * N + col] = v;
        }
    }
}

// ---------------------------------------------------------------------------
// Flash attention (fp32): grid = (ceil(577/64), B*H), 256 threads.
// Q tile 64 rows; KV tiles 32 wide; online softmax; O accumulated in regs.
// All-static smem (~42 KB).
// ---------------------------------------------------------------------------
__global__ __launch_bounds__(256) void attn_ker(const float* __restrict__ qkv,
                                                float* __restrict__ out)
{
    const int bh = blockIdx.y;
    const int b  = bh / NHEAD;
    const int h  = bh % NHEAD;
    const int q0 = blockIdx.x * 64;
    const int t  = threadIdx.x;
    const int ty = t >> 4;   // 0..15 -> 4 O rows each
    const int tx = t & 15;   // 0..15 -> 4 O cols each

    __shared__ float qs[64][65];
    __shared__ float ks[32][65];
    __shared__ float vs[32][65];
    __shared__ float ss[64][33];
    __shared__ float mrow[64], lrow[64], corr[64];

    // load Q tile
    for (int idx = t; idx < 64 * 64; idx += 256) {
        int r = idx >> 6, d = idx & 63;
        int qr = q0 + r;
        qs[r][d] = (qr < SEQ)
            ? qkv[(size_t)(b * SEQ + qr) * C_QKV + h * HDIM + d]
            : 0.f;
    }
    if (t < 64) { mrow[t] = -1e30f; lrow[t] = 0.f; }

    float acc[4][4];
    #pragma unroll
    for (int i = 0; i < 4; i++)
        #pragma unroll
        for (int j = 0; j < 4; j++) acc[i][j] = 0.f;

    for (int j0 = 0; j0 < SEQ; j0 += 32) {
        const int kvlen = min(32, SEQ - j0);
        // load K,V tiles
        for (int idx = t; idx < 32 * 64; idx += 256) {
            int r = idx >> 6, d = idx & 63;
            float kv = 0.f, vv = 0.f;
            if (r < kvlen) {
                size_t base = (size_t)(b * SEQ + j0 + r) * C_QKV + h * HDIM + d;
                kv = qkv[base + 768];
                vv = qkv[base + 1536];
            }
            ks[r][d] = kv;
            vs[r][d] = vv;
        }
        __syncthreads();

        // S tile: rows ty*4+i, cols tx*2+j  (64 x 32)
        float sa[4][2];
        #pragma unroll
        for (int i = 0; i < 4; i++)
            #pragma unroll
            for (int j = 0; j < 2; j++) sa[i][j] = 0.f;
        #pragma unroll 4
        for (int d = 0; d < 64; d++) {
            float aq[4], bk[2];
            #pragma unroll
            for (int i = 0; i < 4; i++) aq[i] = qs[ty * 4 + i][d];
            #pragma unroll
            for (int j = 0; j < 2; j++) bk[j] = ks[tx * 2 + j][d];
            #pragma unroll
            for (int i = 0; i < 4; i++)
                #pragma unroll
                for (int j = 0; j < 2; j++)
                    sa[i][j] += aq[i] * bk[j];
        }
        #pragma unroll
        for (int i = 0; i < 4; i++)
            #pragma unroll
            for (int j = 0; j < 2; j++) {
                int c = tx * 2 + j;
                ss[ty * 4 + i][c] = (c < kvlen) ? sa[i][j] * 0.125f : -1e30f;
            }
        __syncthreads();

        // online softmax update (one thread per row)
        if (t < 64) {
            float mo = mrow[t];
            float mx = mo;
            #pragma unroll 8
            for (int c = 0; c < 32; c++) mx = fmaxf(mx, ss[t][c]);
            float sum = 0.f;
            #pragma unroll 8
            for (int c = 0; c < 32; c++) {
                float p = expf(ss[t][c] - mx);
                ss[t][c] = p;
                sum += p;
            }
            float cr = expf(mo - mx);
            corr[t] = cr;
            mrow[t] = mx;
            lrow[t] = cr * lrow[t] + sum;
        }
        __syncthreads();

        // rescale O and accumulate P @ V
        #pragma unroll
        for (int i = 0; i < 4; i++) {
            float cr = corr[ty * 4 + i];
            #pragma unroll
            for (int j = 0; j < 4; j++) acc[i][j] *= cr;
        }
        for (int k = 0; k < kvlen; k++) {
            float p[4], v[4];
            #pragma unroll
            for (int i = 0; i < 4; i++) p[i] = ss[ty * 4 + i][k];
            #pragma unroll
            for (int j = 0; j < 4; j++) v[j] = vs[k][tx * 4 + j];
            #pragma unroll
            for (int i = 0; i < 4; i++)
                #pragma unroll
                for (int j = 0; j < 4; j++)
                    acc[i][j] += p[i] * v[j];
        }
        __syncthreads();
    }

    // epilogue: divide by l, write [B,N,H,D] contiguous as [MTOK, 768]
    #pragma unroll
    for (int i = 0; i < 4; i++) {
        const int qr = q0 + ty * 4 + i;
        if (qr >= SEQ) continue;
        const float inv = 1.0f / lrow[ty * 4 + i];
        float* orow = out + (size_t)(b * SEQ + qr) * C_EMB + h * HDIM;
        #pragma unroll
        for (int j = 0; j < 4; j++)
            orow[tx * 4 + j] = acc[i][j] * inv;
    }
}

// ---------------------------------------------------------------------------
// Launch
// ---------------------------------------------------------------------------
extern "C" void kernel_launch(void* const* d_in, const int* in_sizes, int n_in,
                              void* d_out, int out_size)
{
    const float* x      = (const float*)d_in[0];
    const float* ln1_g  = (const float*)d_in[1];
    const float* ln1_b  = (const float*)d_in[2];
    const float* w_qkv  = (const float*)d_in[3];
    const float* w_proj = (const float*)d_in[4];
    const float* b_proj = (const float*)d_in[5];
    const float* ln2_g  = (const float*)d_in[6];
    const float* ln2_b  = (const float*)d_in[7];
    const float* w_fc1  = (const float*)d_in[8];
    const float* b_fc1  = (const float*)d_in[9];
    const float* w_fc2  = (const float*)d_in[10];
    const float* b_fc2  = (const float*)d_in[11];
    float* out = (float*)d_out;

    float *p_h, *p_qkv, *p_att, *p_x1, *p_ff;
    cudaGetSymbolAddress((void**)&p_h,   g_h);
    cudaGetSymbolAddress((void**)&p_qkv, g_qkv);
    cudaGetSymbolAddress((void**)&p_att, g_att);
    cudaGetSymbolAddress((void**)&p_x1,  g_x1);
    cudaGetSymbolAddress((void**)&p_ff,  g_ff);

    const int M = MTOK;                       // 36928
    const int gy = (M + 127) / 128;           // 289

    // 1) LN1: x -> h
    ln_ker<<<M, 256>>>(x, ln1_g, ln1_b, p_h);

    // 2) qkv = h @ w_qkv   [M,768] @ [768,2304]
    sgemm_ker<EPI_NONE><<<dim3(C_QKV / 128, gy), 256>>>(
        p_h, w_qkv, nullptr, nullptr, p_qkv, M, C_QKV, C_EMB);

    // 3) attention (flash, per (b,h), q-tiles of 64)
    attn_ker<<<dim3((SEQ + 63) / 64, BATCH * NHEAD), 256>>>(p_qkv, p_att);

    // 4) x1 = x + att @ w_proj + b_proj
    sgemm_ker<EPI_BIAS_RES><<<dim3(C_EMB / 128, gy), 256>>>(
        p_att, w_proj, b_proj, x, p_x1, M, C_EMB, C_EMB);

    // 5) LN2: x1 -> h
    ln_ker<<<M, 256>>>(p_x1, ln2_g, ln2_b, p_h);

    // 6) ff = gelu(h @ w_fc1 + b_fc1)
    sgemm_ker<EPI_BIAS_GELU><<<dim3(C_HID / 128, gy), 256>>>(
        p_h, w_fc1, b_fc1, nullptr, p_ff, M, C_HID, C_EMB);

    // 7) out = x1 + ff @ w_fc2 + b_fc2
    sgemm_ker<EPI_BIAS_RES><<<dim3(C_EMB / 128, gy), 256>>>(
        p_ff, w_fc2, b_fc2, p_x1, out, M, C_EMB, C_HID);
}

// round 4
// speedup vs baseline: 2.3329x; 2.3329x over previous
#include <cuda_runtime.h>
#include <cuda_bf16.h>
#include <math.h>
#include <stdint.h>

// ---------------------------------------------------------------------------
// Problem constants
// ---------------------------------------------------------------------------
#define BATCH   64
#define SEQ     577
#define MTOK    (BATCH * SEQ)      // 36928
#define MPAD    36992              // 289 * 128
#define C_EMB   768
#define C_QKV   2304
#define C_HID   3072
#define NHEAD   12
#define HDIM    64

#define EPI_NONE      0
#define EPI_BIAS_RES  1
#define EPI_BIAS_GELU 2

// ---------------------------------------------------------------------------
// Scratch (device globals)
// ---------------------------------------------------------------------------
__device__ float g_h  [(size_t)MTOK * C_EMB];
__device__ float g_qkv[(size_t)MTOK * C_QKV];
__device__ float g_att[(size_t)MTOK * C_EMB];
__device__ float g_x1 [(size_t)MTOK * C_EMB];
__device__ float g_ff [(size_t)MTOK * C_HID];
// bf16 split operands, chunked+swizzled layout: [K/64][rows][64 bf16], SW128 XOR baked in
__device__ __nv_bfloat16 g_ah[(size_t)MPAD * C_HID];
__device__ __nv_bfloat16 g_al[(size_t)MPAD * C_HID];
__device__ __nv_bfloat16 g_wh[(size_t)C_HID * C_EMB];
__device__ __nv_bfloat16 g_wl[(size_t)C_HID * C_EMB];

// ---------------------------------------------------------------------------
// PTX helpers (sm_90-baseline: bulk-async, mbarrier, ldmatrix, mma.sync)
// ---------------------------------------------------------------------------
__device__ __forceinline__ uint32_t cvta_s(const void* p) {
    uint32_t a;
    asm("{ .reg .u64 t; cvta.to.shared.u64 t, %1; cvt.u32.u64 %0, t; }"
        : "=r"(a) : "l"(p));
    return a;
}
__device__ __forceinline__ void mbar_init(uint32_t mbar, uint32_t cnt) {
    asm volatile("mbarrier.init.shared.b64 [%0], %1;" :: "r"(mbar), "r"(cnt) : "memory");
}
__device__ __forceinline__ void mbar_expect_tx(uint32_t mbar, uint32_t bytes) {
    asm volatile("mbarrier.arrive.expect_tx.shared.b64 _, [%0], %1;"
                 :: "r"(mbar), "r"(bytes) : "memory");
}
__device__ __forceinline__ void mbar_arrive(uint32_t mbar) {
    asm volatile("mbarrier.arrive.shared.b64 _, [%0];" :: "r"(mbar) : "memory");
}
__device__ __forceinline__ void mbar_wait(uint32_t mbar, uint32_t phase) {
    asm volatile(
        "{\n\t"
        ".reg .pred P1;\n\t"
        "WAIT_LOOP_%=:\n\t"
        "mbarrier.try_wait.parity.acquire.cta.shared::cta.b64 P1, [%0], %1, 0x989680;\n\t"
        "@P1 bra.uni WAIT_DONE_%=;\n\t"
        "bra.uni WAIT_LOOP_%=;\n\t"
        "WAIT_DONE_%=:\n\t"
        "}"
        :: "r"(mbar), "r"(phase) : "memory");
}
__device__ __forceinline__ void bulk_ldg(uint32_t dst, const void* src,
                                         uint32_t bytes, uint32_t mbar) {
    asm volatile(
        "cp.async.bulk.shared::cluster.global.mbarrier::complete_tx::bytes "
        "[%0], [%1], %2, [%3];"
        :: "r"(dst), "l"(src), "r"(bytes), "r"(mbar) : "memory");
}
__device__ __forceinline__ void ldsm4(uint32_t* r, uint32_t addr) {
    asm volatile("ldmatrix.sync.aligned.m8n8.x4.shared.b16 {%0,%1,%2,%3}, [%4];"
                 : "=r"(r[0]), "=r"(r[1]), "=r"(r[2]), "=r"(r[3]) : "r"(addr));
}
__device__ __forceinline__ void mma16816(float* c, const uint32_t* a, const uint32_t* b) {
    asm volatile(
        "mma.sync.aligned.m16n8k16.row.col.f32.bf16.bf16.f32 "
        "{%0,%1,%2,%3},{%4,%5,%6,%7},{%8,%9},{%0,%1,%2,%3};"
        : "+f"(c[0]), "+f"(c[1]), "+f"(c[2]), "+f"(c[3])
        : "r"(a[0]), "r"(a[1]), "r"(a[2]), "r"(a[3]), "r"(b[0]), "r"(b[1]));
}

// ---------------------------------------------------------------------------
// LayerNorm (R1-verified)
// ---------------------------------------------------------------------------
__global__ __launch_bounds__(256) void ln_ker(const float* __restrict__ x,
                                              const float* __restrict__ gamma,
                                              const float* __restrict__ beta,
                                              float* __restrict__ o)
{
    const int row = blockIdx.x;
    const float* xr = x + (size_t)row * C_EMB;
    float s = 0.f, s2 = 0.f;
    #pragma unroll
    for (int c = threadIdx.x; c < C_EMB; c += 256) {
        float v = xr[c];
        s += v; s2 += v * v;
    }
    #pragma unroll
    for (int off = 16; off > 0; off >>= 1) {
        s  += __shfl_down_sync(0xFFFFFFFFu, s,  off);
        s2 += __shfl_down_sync(0xFFFFFFFFu, s2, off);
    }
    __shared__ float shs[8], shs2[8];
    const int lane = threadIdx.x & 31, warp = threadIdx.x >> 5;
    if (lane == 0) { shs[warp] = s; shs2[warp] = s2; }
    __syncthreads();
    if (threadIdx.x == 0) {
        float ts = 0.f, ts2 = 0.f;
        #pragma unroll
        for (int w = 0; w < 8; w++) { ts += shs[w]; ts2 += shs2[w]; }
        float mean = ts * (1.0f / C_EMB);
        float var  = ts2 * (1.0f / C_EMB) - mean * mean;
        shs[0]  = mean;
        shs2[0] = rsqrtf(var + 1e-5f);
    }
    __syncthreads();
    const float mean = shs[0], rstd = shs2[0];
    float* orow = o + (size_t)row * C_EMB;
    #pragma unroll
    for (int c = threadIdx.x; c < C_EMB; c += 256)
        orow[c] = (xr[c] - mean) * rstd * gamma[c] + beta[c];
}

// ---------------------------------------------------------------------------
// split_act: fp32 [MTOK,K] -> hi/lo bf16 chunked swizzled layout
// byte(m,k) = ((k>>6)*MPAD + m)*128 + (((k&63)*2) ^ ((m&7)<<4))
// ---------------------------------------------------------------------------
__global__ __launch_bounds__(256) void split_act_ker(const float* __restrict__ x,
                                                     uint8_t* __restrict__ hi,
                                                     uint8_t* __restrict__ lo,
                                                     int K)
{
    const int kq_per_row = K >> 3;
    int idx = blockIdx.x * 256 + threadIdx.x;
    if (idx >= MTOK * kq_per_row) return;
    int m  = idx / kq_per_row;
    int k  = (idx - m * kq_per_row) << 3;
    const float4* xp = (const float4*)(x + (size_t)m * K + k);
    float4 v0 = xp[0], v1 = xp[1];
    float v[8] = {v0.x, v0.y, v0.z, v0.w, v1.x, v1.y, v1.z, v1.w};
    union { __nv_bfloat16 b[8]; uint4 u; } uh, ul;
    #pragma unroll
    for (int i = 0; i < 8; i++) {
        __nv_bfloat16 h = __float2bfloat16(v[i]);
        uh.b[i] = h;
        ul.b[i] = __float2bfloat16(v[i] - __bfloat162float(h));
    }
    size_t base = ((size_t)(k >> 6) * MPAD + m) * 128
                + ((uint32_t)((k & 63) * 2) ^ (uint32_t)((m & 7) << 4));
    *(uint4*)(hi + base) = uh.u;
    *(uint4*)(lo + base) = ul.u;
}

// ---------------------------------------------------------------------------
// splitT: fp32 weights [K,N] -> transposed hi/lo bf16 chunked swizzled [K/64][N][64]
// byte(n,k) = ((k>>6)*N + n)*128 + (((k&63)*2) ^ ((n&7)<<4))
// ---------------------------------------------------------------------------
__global__ void splitT_ker(const float* __restrict__ w,
                           uint8_t* __restrict__ hi, uint8_t* __restrict__ lo,
                           int K, int N)
{
    __shared__ float tile[32][33];
    const int n0 = blockIdx.x * 32, k0 = blockIdx.y * 32;
    const int tx = threadIdx.x, ty = threadIdx.y;
    for (int i = ty; i < 32; i += 4)
        tile[i][tx] = w[(size_t)(k0 + i) * N + n0 + tx];
    __syncthreads();
    const int n = n0 + tx;
    const int k = k0 + ty * 8;
    union { __nv_bfloat16 b[8]; uint4 u; } uh, ul;
    #pragma unroll
    for (int i = 0; i < 8; i++) {
        float v = tile[ty * 8 + i][tx];
        __nv_bfloat16 h = __float2bfloat16(v);
        uh.b[i] = h;
        ul.b[i] = __float2bfloat16(v - __bfloat162float(h));
    }
    size_t base = ((size_t)(k >> 6) * N + n) * 128
                + ((uint32_t)((k & 63) * 2) ^ (uint32_t)((n & 7) << 4));
    *(uint4*)(hi + base) = uh.u;
    *(uint4*)(lo + base) = ul.u;
}

// ---------------------------------------------------------------------------
// bf16-split warp-MMA GEMM: C = A@B  (hh + hl + lh passes, fp32 reg accum)
// BM=128, BN=128, BK=64, 256 thr (8 warps 4x2, warp tile 32x64),
// 2-stage cp.async.bulk + mbarrier pipeline.
// ---------------------------------------------------------------------------
#define STAGE_BYTES 65536   // Ah 16K | Al 16K | Bh 16K | Bl 16K
#define GEMM_SMEM   (2 * STAGE_BYTES + 1024)

__device__ __forceinline__ void gemm_pass(uint32_t aB, uint32_t bB,
                                          const uint32_t rta[2], const uint32_t rtb[4],
                                          uint32_t khA16, uint32_t khB16, uint32_t sw,
                                          float (&acc)[2][8][4])
{
    #pragma unroll
    for (int ks = 0; ks < 4; ks++) {
        const uint32_t offA = (uint32_t)(ks * 32 + khA16) ^ sw;
        const uint32_t offB = (uint32_t)(ks * 32 + khB16) ^ sw;
        uint32_t a[2][4], b[4][4];
        ldsm4(a[0], aB + rta[0] + offA);
        ldsm4(a[1], aB + rta[1] + offA);
        #pragma unroll
        for (int j = 0; j < 4; j++)
            ldsm4(b[j], bB + rtb[j] + offB);
        #pragma unroll
        for (int mi = 0; mi < 2; mi++)
            #pragma unroll
            for (int j = 0; j < 4; j++) {
                mma16816(acc[mi][2 * j],     a[mi], &b[j][0]);
                mma16816(acc[mi][2 * j + 1], a[mi], &b[j][2]);
            }
    }
}

template<int EPI>
__global__ __launch_bounds__(256, 1) void gemm_mma_ker(
    const uint8_t* __restrict__ Ah, const uint8_t* __restrict__ Al,
    const uint8_t* __restrict__ Bh, const uint8_t* __restrict__ Bl,
    const float* __restrict__ bias, const float* __restrict__ res,
    float* __restrict__ C, int M, int N, int K)
{
    extern __shared__ uint8_t dynsmem[];
    __shared__ __align__(8) uint64_t s_bar[4];

    const int t = threadIdx.x, lane = t & 31, wid = t >> 5;
    const int wm = wid >> 1, wn = wid & 1;
    const int bm = blockIdx.y * 128, bn = blockIdx.x * 128;

    const uint32_t sbase = (cvta_s(dynsmem) + 1023u) & ~1023u;
    uint32_t bfull[2]  = { cvta_s(&s_bar[0]), cvta_s(&s_bar[1]) };
    uint32_t bempty[2] = { cvta_s(&s_bar[2]), cvta_s(&s_bar[3]) };

    if (t == 0) {
        mbar_init(bfull[0], 1);  mbar_init(bfull[1], 1);
        mbar_init(bempty[0], 8); mbar_init(bempty[1], 8);
    }
    __syncthreads();

    const int nc = K >> 6;
    auto issue = [&](int c) {
        const int s = c & 1;
        const uint32_t sb = sbase + (uint32_t)s * STAGE_BYTES;
        mbar_expect_tx(bfull[s], STAGE_BYTES);
        bulk_ldg(sb,         Ah + ((size_t)c * MPAD + bm) * 128, 16384, bfull[s]);
        bulk_ldg(sb + 16384, Al + ((size_t)c * MPAD + bm) * 128, 16384, bfull[s]);
        bulk_ldg(sb + 32768, Bh + ((size_t)c * N + bn) * 128,    16384, bfull[s]);
        bulk_ldg(sb + 49152, Bl + ((size_t)c * N + bn) * 128,    16384, bfull[s]);
    };
    if (t == 0) { issue(0); if (nc > 1) issue(1); }

    // per-lane invariants for ldmatrix addressing
    const uint32_t sw = (uint32_t)(lane & 7) << 4;
    uint32_t rta[2], rtb[4];
    {
        const int rowoff = ((lane >> 3) & 1) * 8 + (lane & 7);
        rta[0] = (uint32_t)(wm * 32 +  0 + rowoff) * 128;
        rta[1] = (uint32_t)(wm * 32 + 16 + rowoff) * 128;
        const int nt = lane >> 4;
        #pragma unroll
        for (int j = 0; j < 4; j++)
            rtb[j] = (uint32_t)(wn * 64 + (2 * j + nt) * 8 + (lane & 7)) * 128;
    }
    const uint32_t khA16 = (uint32_t)(lane >> 4) * 16;
    const uint32_t khB16 = (uint32_t)((lane >> 3) & 1) * 16;

    float acc[2][8][4];
    #pragma unroll
    for (int mi = 0; mi < 2; mi++)
        #pragma unroll
        for (int ni = 0; ni < 8; ni++)
            #pragma unroll
            for (int r = 0; r < 4; r++) acc[mi][ni][r] = 0.f;

    int fph[2] = {0, 0}, eph[2] = {0, 0};
    for (int c = 0; c < nc; c++) {
        const int s = c & 1;
        mbar_wait(bfull[s], fph[s]); fph[s] ^= 1;
        const uint32_t sb = sbase + (uint32_t)s * STAGE_BYTES;
        gemm_pass(sb,         sb + 32768, rta, rtb, khA16, khB16, sw, acc); // hh
        gemm_pass(sb,         sb + 49152, rta, rtb, khA16, khB16, sw, acc); // hl
        gemm_pass(sb + 16384, sb + 32768, rta, rtb, khA16, khB16, sw, acc); // lh
        if (lane == 0) mbar_arrive(bempty[s]);
        if (t == 0 && c + 2 < nc) {
            mbar_wait(bempty[s], eph[s]); eph[s] ^= 1;
            issue(c + 2);
        }
    }

    // epilogue
    const int row0 = bm + wm * 32 + (lane >> 2);
    const int col0 = bn + wn * 64 + (lane & 3) * 2;
    #pragma unroll
    for (int mi = 0; mi < 2; mi++) {
        #pragma unroll
        for (int ni = 0; ni < 8; ni++) {
            const int col = col0 + ni * 8;
            float bb0 = 0.f, bb1 = 0.f;
            if (EPI != EPI_NONE) { bb0 = bias[col]; bb1 = bias[col + 1]; }
            #pragma unroll
            for (int half = 0; half < 2; half++) {
                const int row = row0 + mi * 16 + half * 8;
                if (row < M) {
                    float v0 = acc[mi][ni][half * 2];
                    float v1 = acc[mi][ni][half * 2 + 1];
                    if (EPI != EPI_NONE) { v0 += bb0; v1 += bb1; }
                    if (EPI == EPI_BIAS_GELU) {
                        v0 = 0.5f * v0 * (1.0f + erff(v0 * 0.70710678118654752f));
                        v1 = 0.5f * v1 * (1.0f + erff(v1 * 0.70710678118654752f));
                    }
                    if (EPI == EPI_BIAS_RES) {
                        const float2 r2 = *(const float2*)(res + (size_t)row * N + col);
                        v0 += r2.x; v1 += r2.y;
                    }
                    *(float2*)(C + (size_t)row * N + col) = make_float2(v0, v1);
                }
            }
        }
    }
}

// ---------------------------------------------------------------------------
// Flash attention (fp32, R1-verified)
// ---------------------------------------------------------------------------
__global__ __launch_bounds__(256) void attn_ker(const float* __restrict__ qkv,
                                                float* __restrict__ out)
{
    const int bh = blockIdx.y;
    const int b  = bh / NHEAD;
    const int h  = bh % NHEAD;
    const int q0 = blockIdx.x * 64;
    const int t  = threadIdx.x;
    const int ty = t >> 4;
    const int tx = t & 15;

    __shared__ float qs[64][65];
    __shared__ float ks[32][65];
    __shared__ float vs[32][65];
    __shared__ float ss[64][33];
    __shared__ float mrow[64], lrow[64], corr[64];

    for (int idx = t; idx < 64 * 64; idx += 256) {
        int r = idx >> 6, d = idx & 63;
        int qr = q0 + r;
        qs[r][d] = (qr < SEQ)
            ? qkv[(size_t)(b * SEQ + qr) * C_QKV + h * HDIM + d]
            : 0.f;
    }
    if (t < 64) { mrow[t] = -1e30f; lrow[t] = 0.f; }

    float acc[4][4];
    #pragma unroll
    for (int i = 0; i < 4; i++)
        #pragma unroll
        for (int j = 0; j < 4; j++) acc[i][j] = 0.f;

    for (int j0 = 0; j0 < SEQ; j0 += 32) {
        const int kvlen = min(32, SEQ - j0);
        for (int idx = t; idx < 32 * 64; idx += 256) {
            int r = idx >> 6, d = idx & 63;
            float kv = 0.f, vv = 0.f;
            if (r < kvlen) {
                size_t base = (size_t)(b * SEQ + j0 + r) * C_QKV + h * HDIM + d;
                kv = qkv[base + 768];
                vv = qkv[base + 1536];
            }
            ks[r][d] = kv;
            vs[r][d] = vv;
        }
        __syncthreads();

        float sa[4][2];
        #pragma unroll
        for (int i = 0; i < 4; i++)
            #pragma unroll
            for (int j = 0; j < 2; j++) sa[i][j] = 0.f;
        #pragma unroll 4
        for (int d = 0; d < 64; d++) {
            float aq[4], bk[2];
            #pragma unroll
            for (int i = 0; i < 4; i++) aq[i] = qs[ty * 4 + i][d];
            #pragma unroll
            for (int j = 0; j < 2; j++) bk[j] = ks[tx * 2 + j][d];
            #pragma unroll
            for (int i = 0; i < 4; i++)
                #pragma unroll
                for (int j = 0; j < 2; j++)
                    sa[i][j] += aq[i] * bk[j];
        }
        #pragma unroll
        for (int i = 0; i < 4; i++)
            #pragma unroll
            for (int j = 0; j < 2; j++) {
                int c = tx * 2 + j;
                ss[ty * 4 + i][c] = (c < kvlen) ? sa[i][j] * 0.125f : -1e30f;
            }
        __syncthreads();

        if (t < 64) {
            float mo = mrow[t];
            float mx = mo;
            #pragma unroll 8
            for (int c = 0; c < 32; c++) mx = fmaxf(mx, ss[t][c]);
            float sum = 0.f;
            #pragma unroll 8
            for (int c = 0; c < 32; c++) {
                float p = expf(ss[t][c] - mx);
                ss[t][c] = p;
                sum += p;
            }
            float cr = expf(mo - mx);
            corr[t] = cr;
            mrow[t] = mx;
            lrow[t] = cr * lrow[t] + sum;
        }
        __syncthreads();

        #pragma unroll
        for (int i = 0; i < 4; i++) {
            float cr = corr[ty * 4 + i];
            #pragma unroll
            for (int j = 0; j < 4; j++) acc[i][j] *= cr;
        }
        for (int k = 0; k < kvlen; k++) {
            float p[4], v[4];
            #pragma unroll
            for (int i = 0; i < 4; i++) p[i] = ss[ty * 4 + i][k];
            #pragma unroll
            for (int j = 0; j < 4; j++) v[j] = vs[k][tx * 4 + j];
            #pragma unroll
            for (int i = 0; i < 4; i++)
                #pragma unroll
                for (int j = 0; j < 4; j++)
                    acc[i][j] += p[i] * v[j];
        }
        __syncthreads();
    }

    #pragma unroll
    for (int i = 0; i < 4; i++) {
        const int qr = q0 + ty * 4 + i;
        if (qr >= SEQ) continue;
        const float inv = 1.0f / lrow[ty * 4 + i];
        float* orow = out + (size_t)(b * SEQ + qr) * C_EMB + h * HDIM;
        #pragma unroll
        for (int j = 0; j < 4; j++)
            orow[tx * 4 + j] = acc[i][j] * inv;
    }
}

// ---------------------------------------------------------------------------
// Launch
// ---------------------------------------------------------------------------
extern "C" void kernel_launch(void* const* d_in, const int* in_sizes, int n_in,
                              void* d_out, int out_size)
{
    const float* x      = (const float*)d_in[0];
    const float* ln1_g  = (const float*)d_in[1];
    const float* ln1_b  = (const float*)d_in[2];
    const float* w_qkv  = (const float*)d_in[3];
    const float* w_proj = (const float*)d_in[4];
    const float* b_proj = (const float*)d_in[5];
    const float* ln2_g  = (const float*)d_in[6];
    const float* ln2_b  = (const float*)d_in[7];
    const float* w_fc1  = (const float*)d_in[8];
    const float* b_fc1  = (const float*)d_in[9];
    const float* w_fc2  = (const float*)d_in[10];
    const float* b_fc2  = (const float*)d_in[11];
    float* out = (float*)d_out;

    float *p_h, *p_qkv, *p_att, *p_x1, *p_ff;
    uint8_t *p_ah, *p_al, *p_wh, *p_wl;
    cudaGetSymbolAddress((void**)&p_h,   g_h);
    cudaGetSymbolAddress((void**)&p_qkv, g_qkv);
    cudaGetSymbolAddress((void**)&p_att, g_att);
    cudaGetSymbolAddress((void**)&p_x1,  g_x1);
    cudaGetSymbolAddress((void**)&p_ff,  g_ff);
    cudaGetSymbolAddress((void**)&p_ah,  g_ah);
    cudaGetSymbolAddress((void**)&p_al,  g_al);
    cudaGetSymbolAddress((void**)&p_wh,  g_wh);
    cudaGetSymbolAddress((void**)&p_wl,  g_wl);

    cudaFuncSetAttribute(gemm_mma_ker<EPI_NONE>,
                         cudaFuncAttributeMaxDynamicSharedMemorySize, GEMM_SMEM);
    cudaFuncSetAttribute(gemm_mma_ker<EPI_BIAS_RES>,
                         cudaFuncAttributeMaxDynamicSharedMemorySize, GEMM_SMEM);
    cudaFuncSetAttribute(gemm_mma_ker<EPI_BIAS_GELU>,
                         cudaFuncAttributeMaxDynamicSharedMemorySize, GEMM_SMEM);

    const int M = MTOK;
    const int MY = (M + 127) / 128;   // 289
    const dim3 blkT(32, 4);

    // 1) LN1
    ln_ker<<<M, 256>>>(x, ln1_g, ln1_b, p_h);
    // 2) split activations (K=768)
    split_act_ker<<<(M * (C_EMB / 8) + 255) / 256, 256>>>(p_h, p_ah, p_al, C_EMB);
    // 3) split+transpose w_qkv [768,2304]
    splitT_ker<<<dim3(C_QKV / 32, C_EMB / 32), blkT>>>(w_qkv, p_wh, p_wl, C_EMB, C_QKV);
    // 4) qkv GEMM  M x 2304 x 768
    gemm_mma_ker<EPI_NONE><<<dim3(C_QKV / 128, MY), 256, GEMM_SMEM>>>(
        p_ah, p_al, p_wh, p_wl, nullptr, nullptr, p_qkv, M, C_QKV, C_EMB);
    // 5) attention
    attn_ker<<<dim3((SEQ + 63) / 64, BATCH * NHEAD), 256>>>(p_qkv, p_att);
    // 6) split att, w_proj
    split_act_ker<<<(M * (C_EMB / 8) + 255) / 256, 256>>>(p_att, p_ah, p_al, C_EMB);
    splitT_ker<<<dim3(C_EMB / 32, C_EMB / 32), blkT>>>(w_proj, p_wh, p_wl, C_EMB, C_EMB);
    // 7) x1 = x + att @ w_proj + b_proj
    gemm_mma_ker<EPI_BIAS_RES><<<dim3(C_EMB / 128, MY), 256, GEMM_SMEM>>>(
        p_ah, p_al, p_wh, p_wl, b_proj, x, p_x1, M, C_EMB, C_EMB);
    // 8) LN2
    ln_ker<<<M, 256>>>(p_x1, ln2_g, ln2_b, p_h);
    // 9) split h, w_fc1
    split_act_ker<<<(M * (C_EMB / 8) + 255) / 256, 256>>>(p_h, p_ah, p_al, C_EMB);
    splitT_ker<<<dim3(C_HID / 32, C_EMB / 32), blkT>>>(w_fc1, p_wh, p_wl, C_EMB, C_HID);
    // 10) ff = gelu(h @ w_fc1 + b_fc1)   M x 3072 x 768
    gemm_mma_ker<EPI_BIAS_GELU><<<dim3(C_HID / 128, MY), 256, GEMM_SMEM>>>(
        p_ah, p_al, p_wh, p_wl, b_fc1, nullptr, p_ff, M, C_HID, C_EMB);
    // 11) split ff (K=3072), w_fc2
    split_act_ker<<<(M * (C_HID / 8) + 255) / 256, 256>>>(p_ff, p_ah, p_al, C_HID);
    splitT_ker<<<dim3(C_EMB / 32, C_HID / 32), blkT>>>(w_fc2, p_wh, p_wl, C_HID, C_EMB);
    // 12) out = x1 + ff @ w_fc2 + b_fc2   M x 768 x 3072
    gemm_mma_ker<EPI_BIAS_RES><<<dim3(C_EMB / 128, MY), 256, GEMM_SMEM>>>(
        p_ah, p_al, p_wh, p_wl, b_fc2, p_x1, out, M, C_EMB, C_HID);
}

// round 5
// speedup vs baseline: 3.8096x; 1.6330x over previous
#include <cuda_runtime.h>
#include <cuda_bf16.h>
#include <cuda_fp16.h>
#include <math.h>
#include <stdint.h>

// ---------------------------------------------------------------------------
// Problem constants
// ---------------------------------------------------------------------------
#define BATCH   64
#define SEQ     577
#define MTOK    (BATCH * SEQ)      // 36928
#define MPAD    36992              // 289 * 128
#define C_EMB   768
#define C_QKV   2304
#define C_HID   3072
#define NHEAD   12
#define HDIM    64

#define EPI_BIAS_RES        1
#define EPI_BIAS_GELU_SPLIT 2
#define EPI_HALF            3

// ---------------------------------------------------------------------------
// Scratch (device globals)
// ---------------------------------------------------------------------------
__device__ __half g_qkvh[(size_t)MTOK * C_QKV];            // qkv proj, fp16
__device__ float  g_x1 [(size_t)MTOK * C_EMB];             // residual 1
// split activation operands, chunked+swizzled: [K/64][MPAD rows][64 bf16]
__device__ __nv_bfloat16 g_ah[(size_t)MPAD * C_EMB];       // pair A (K=768 acts)
__device__ __nv_bfloat16 g_al[(size_t)MPAD * C_EMB];
__device__ __nv_bfloat16 g_bh[(size_t)MPAD * C_HID];       // pair B (ff acts)
__device__ __nv_bfloat16 g_bl[(size_t)MPAD * C_HID];
// split weights, chunked+swizzled: [K/64][N][64 bf16]
__device__ __nv_bfloat16 g_wh[(size_t)C_HID * C_EMB];
__device__ __nv_bfloat16 g_wl[(size_t)C_HID * C_EMB];

// ---------------------------------------------------------------------------
// PTX helpers
// ---------------------------------------------------------------------------
__device__ __forceinline__ uint32_t cvta_s(const void* p) {
    uint32_t a;
    asm("{ .reg .u64 t; cvta.to.shared.u64 t, %1; cvt.u32.u64 %0, t; }"
        : "=r"(a) : "l"(p));
    return a;
}
__device__ __forceinline__ void mbar_init(uint32_t mbar, uint32_t cnt) {
    asm volatile("mbarrier.init.shared.b64 [%0], %1;" :: "r"(mbar), "r"(cnt) : "memory");
}
__device__ __forceinline__ void mbar_expect_tx(uint32_t mbar, uint32_t bytes) {
    asm volatile("mbarrier.arrive.expect_tx.shared.b64 _, [%0], %1;"
                 :: "r"(mbar), "r"(bytes) : "memory");
}
__device__ __forceinline__ void mbar_arrive(uint32_t mbar) {
    asm volatile("mbarrier.arrive.shared.b64 _, [%0];" :: "r"(mbar) : "memory");
}
__device__ __forceinline__ void mbar_wait(uint32_t mbar, uint32_t phase) {
    asm volatile(
        "{\n\t"
        ".reg .pred P1;\n\t"
        "WAIT_LOOP_%=:\n\t"
        "mbarrier.try_wait.parity.acquire.cta.shared::cta.b64 P1, [%0], %1, 0x989680;\n\t"
        "@P1 bra.uni WAIT_DONE_%=;\n\t"
        "bra.uni WAIT_LOOP_%=;\n\t"
        "WAIT_DONE_%=:\n\t"
        "}"
        :: "r"(mbar), "r"(phase) : "memory");
}
__device__ __forceinline__ void bulk_ldg(uint32_t dst, const void* src,
                                         uint32_t bytes, uint32_t mbar) {
    asm volatile(
        "cp.async.bulk.shared::cluster.global.mbarrier::complete_tx::bytes "
        "[%0], [%1], %2, [%3];"
        :: "r"(dst), "l"(src), "r"(bytes), "r"(mbar) : "memory");
}
__device__ __forceinline__ void ldsm4(uint32_t* r, uint32_t addr) {
    asm volatile("ldmatrix.sync.aligned.m8n8.x4.shared.b16 {%0,%1,%2,%3}, [%4];"
                 : "=r"(r[0]), "=r"(r[1]), "=r"(r[2]), "=r"(r[3]) : "r"(addr));
}
__device__ __forceinline__ void ldsm4t(uint32_t* r, uint32_t addr) {
    asm volatile("ldmatrix.sync.aligned.m8n8.x4.trans.shared.b16 {%0,%1,%2,%3}, [%4];"
                 : "=r"(r[0]), "=r"(r[1]), "=r"(r[2]), "=r"(r[3]) : "r"(addr));
}
__device__ __forceinline__ void mma_bf16(float* c, const uint32_t* a, const uint32_t* b) {
    asm volatile(
        "mma.sync.aligned.m16n8k16.row.col.f32.bf16.bf16.f32 "
        "{%0,%1,%2,%3},{%4,%5,%6,%7},{%8,%9},{%0,%1,%2,%3};"
        : "+f"(c[0]), "+f"(c[1]), "+f"(c[2]), "+f"(c[3])
        : "r"(a[0]), "r"(a[1]), "r"(a[2]), "r"(a[3]), "r"(b[0]), "r"(b[1]));
}
__device__ __forceinline__ void mma_f16(float* c, const uint32_t* a, const uint32_t* b) {
    asm volatile(
        "mma.sync.aligned.m16n8k16.row.col.f32.f16.f16.f32 "
        "{%0,%1,%2,%3},{%4,%5,%6,%7},{%8,%9},{%0,%1,%2,%3};"
        : "+f"(c[0]), "+f"(c[1]), "+f"(c[2]), "+f"(c[3])
        : "r"(a[0]), "r"(a[1]), "r"(a[2]), "r"(a[3]), "r"(b[0]), "r"(b[1]));
}

__device__ __forceinline__ uint32_t pack_bf2(float a, float b) {
    __nv_bfloat162 r = __floats2bfloat162_rn(a, b);
    return *(uint32_t*)&r;
}
__device__ __forceinline__ void split_pair(float v0, float v1, uint32_t& hi, uint32_t& lo) {
    __nv_bfloat16 h0 = __float2bfloat16(v0);
    __nv_bfloat16 h1 = __float2bfloat16(v1);
    __nv_bfloat162 hh; hh.x = h0; hh.y = h1;
    hi = *(uint32_t*)&hh;
    lo = pack_bf2(v0 - __bfloat162float(h0), v1 - __bfloat162float(h1));
}

// ---------------------------------------------------------------------------
// Fused LayerNorm + bf16 hi/lo split (K=768) -> pair A chunked swizzled
// ---------------------------------------------------------------------------
__global__ __launch_bounds__(256) void ln_split_ker(const float* __restrict__ x,
                                                    const float* __restrict__ gamma,
                                                    const float* __restrict__ beta,
                                                    uint8_t* __restrict__ hi,
                                                    uint8_t* __restrict__ lo)
{
    const int row = blockIdx.x;
    const float* xr = x + (size_t)row * C_EMB;
    float s = 0.f, s2 = 0.f;
    #pragma unroll
    for (int c = threadIdx.x; c < C_EMB; c += 256) {
        float v = xr[c];
        s += v; s2 += v * v;
    }
    #pragma unroll
    for (int off = 16; off > 0; off >>= 1) {
        s  += __shfl_down_sync(0xFFFFFFFFu, s,  off);
        s2 += __shfl_down_sync(0xFFFFFFFFu, s2, off);
    }
    __shared__ float shs[8], shs2[8];
    const int lane = threadIdx.x & 31, warp = threadIdx.x >> 5;
    if (lane == 0) { shs[warp] = s; shs2[warp] = s2; }
    __syncthreads();
    if (threadIdx.x == 0) {
        float ts = 0.f, ts2 = 0.f;
        #pragma unroll
        for (int w = 0; w < 8; w++) { ts += shs[w]; ts2 += shs2[w]; }
        float mean = ts * (1.0f / C_EMB);
        float var  = ts2 * (1.0f / C_EMB) - mean * mean;
        shs[0]  = mean;
        shs2[0] = rsqrtf(var + 1e-5f);
    }
    __syncthreads();
    const float mean = shs[0], rstd = shs2[0];
    if (threadIdx.x < 96) {
        const int k = threadIdx.x * 8;
        union { __nv_bfloat16 b[8]; uint4 u; } uh, ul;
        #pragma unroll
        for (int i = 0; i < 8; i++) {
            float v = (xr[k + i] - mean) * rstd * gamma[k + i] + beta[k + i];
            __nv_bfloat16 h = __float2bfloat16(v);
            uh.b[i] = h;
            ul.b[i] = __float2bfloat16(v - __bfloat162float(h));
        }
        size_t base = ((size_t)(k >> 6) * MPAD + row) * 128
                    + ((uint32_t)((k & 63) * 2) ^ (uint32_t)((row & 7) << 4));
        *(uint4*)(hi + base) = uh.u;
        *(uint4*)(lo + base) = ul.u;
    }
}

// ---------------------------------------------------------------------------
// splitT: fp32 weights [K,N] -> transposed hi/lo bf16 chunked swizzled [K/64][N][64]
// ---------------------------------------------------------------------------
__global__ void splitT_ker(const float* __restrict__ w,
                           uint8_t* __restrict__ hi, uint8_t* __restrict__ lo,
                           int K, int N)
{
    __shared__ float tile[32][33];
    const int n0 = blockIdx.x * 32, k0 = blockIdx.y * 32;
    const int tx = threadIdx.x, ty = threadIdx.y;
    for (int i = ty; i < 32; i += 4)
        tile[i][tx] = w[(size_t)(k0 + i) * N + n0 + tx];
    __syncthreads();
    const int n = n0 + tx;
    const int k = k0 + ty * 8;
    union { __nv_bfloat16 b[8]; uint4 u; } uh, ul;
    #pragma unroll
    for (int i = 0; i < 8; i++) {
        float v = tile[ty * 8 + i][tx];
        __nv_bfloat16 h = __float2bfloat16(v);
        uh.b[i] = h;
        ul.b[i] = __float2bfloat16(v - __bfloat162float(h));
    }
    size_t base = ((size_t)(k >> 6) * N + n) * 128
                + ((uint32_t)((k & 63) * 2) ^ (uint32_t)((n & 7) << 4));
    *(uint4*)(hi + base) = uh.u;
    *(uint4*)(lo + base) = ul.u;
}

// ---------------------------------------------------------------------------
// bf16-split warp-MMA GEMM (hh+hl+lh), 2-stage cp.async.bulk pipeline.
// Epilogues: fp32+bias+res | bias+GELU+split-out | fp16-out
// ---------------------------------------------------------------------------
#define STAGE_BYTES 65536
#define GEMM_SMEM   (2 * STAGE_BYTES + 1024)

__device__ __forceinline__ void gemm_pass(uint32_t aB, uint32_t bB,
                                          const uint32_t rta[2], const uint32_t rtb[4],
                                          uint32_t khA16, uint32_t khB16, uint32_t sw,
                                          float (&acc)[2][8][4])
{
    #pragma unroll
    for (int ks = 0; ks < 4; ks++) {
        const uint32_t offA = (uint32_t)(ks * 32 + khA16) ^ sw;
        const uint32_t offB = (uint32_t)(ks * 32 + khB16) ^ sw;
        uint32_t a[2][4], b[4][4];
        ldsm4(a[0], aB + rta[0] + offA);
        ldsm4(a[1], aB + rta[1] + offA);
        #pragma unroll
        for (int j = 0; j < 4; j++)
            ldsm4(b[j], bB + rtb[j] + offB);
        #pragma unroll
        for (int mi = 0; mi < 2; mi++)
            #pragma unroll
            for (int j = 0; j < 4; j++) {
                mma_bf16(acc[mi][2 * j],     a[mi], &b[j][0]);
                mma_bf16(acc[mi][2 * j + 1], a[mi], &b[j][2]);
            }
    }
}

template<int EPI>
__global__ __launch_bounds__(256, 1) void gemm_mma_ker(
    const uint8_t* __restrict__ Ah, const uint8_t* __restrict__ Al,
    const uint8_t* __restrict__ Bh, const uint8_t* __restrict__ Bl,
    const float* __restrict__ bias, const float* __restrict__ res,
    float* __restrict__ C, __half* __restrict__ Ch,
    uint8_t* __restrict__ Sh, uint8_t* __restrict__ Sl,
    int M, int N, int K)
{
    extern __shared__ uint8_t dynsmem[];
    __shared__ __align__(8) uint64_t s_bar[4];

    const int t = threadIdx.x, lane = t & 31, wid = t >> 5;
    const int wm = wid >> 1, wn = wid & 1;
    const int bm = blockIdx.y * 128, bn = blockIdx.x * 128;

    const uint32_t sbase = (cvta_s(dynsmem) + 1023u) & ~1023u;
    uint32_t bfull[2]  = { cvta_s(&s_bar[0]), cvta_s(&s_bar[1]) };
    uint32_t bempty[2] = { cvta_s(&s_bar[2]), cvta_s(&s_bar[3]) };

    if (t == 0) {
        mbar_init(bfull[0], 1);  mbar_init(bfull[1], 1);
        mbar_init(bempty[0], 8); mbar_init(bempty[1], 8);
    }
    __syncthreads();

    const int nc = K >> 6;
    auto issue = [&](int c) {
        const int s = c & 1;
        const uint32_t sb = sbase + (uint32_t)s * STAGE_BYTES;
        mbar_expect_tx(bfull[s], STAGE_BYTES);
        bulk_ldg(sb,         Ah + ((size_t)c * MPAD + bm) * 128, 16384, bfull[s]);
        bulk_ldg(sb + 16384, Al + ((size_t)c * MPAD + bm) * 128, 16384, bfull[s]);
        bulk_ldg(sb + 32768, Bh + ((size_t)c * N + bn) * 128,    16384, bfull[s]);
        bulk_ldg(sb + 49152, Bl + ((size_t)c * N + bn) * 128,    16384, bfull[s]);
    };
    if (t == 0) { issue(0); if (nc > 1) issue(1); }

    const uint32_t sw = (uint32_t)(lane & 7) << 4;
    uint32_t rta[2], rtb[4];
    {
        const int rowoff = ((lane >> 3) & 1) * 8 + (lane & 7);
        rta[0] = (uint32_t)(wm * 32 +  0 + rowoff) * 128;
        rta[1] = (uint32_t)(wm * 32 + 16 + rowoff) * 128;
        const int nt = lane >> 4;
        #pragma unroll
        for (int j = 0; j < 4; j++)
            rtb[j] = (uint32_t)(wn * 64 + (2 * j + nt) * 8 + (lane & 7)) * 128;
    }
    const uint32_t khA16 = (uint32_t)(lane >> 4) * 16;
    const uint32_t khB16 = (uint32_t)((lane >> 3) & 1) * 16;

    float acc[2][8][4];
    #pragma unroll
    for (int mi = 0; mi < 2; mi++)
        #pragma unroll
        for (int ni = 0; ni < 8; ni++)
            #pragma unroll
            for (int r = 0; r < 4; r++) acc[mi][ni][r] = 0.f;

    int fph[2] = {0, 0}, eph[2] = {0, 0};
    for (int c = 0; c < nc; c++) {
        const int s = c & 1;
        mbar_wait(bfull[s], fph[s]); fph[s] ^= 1;
        const uint32_t sb = sbase + (uint32_t)s * STAGE_BYTES;
        gemm_pass(sb,         sb + 32768, rta, rtb, khA16, khB16, sw, acc); // hh
        gemm_pass(sb,         sb + 49152, rta, rtb, khA16, khB16, sw, acc); // hl
        gemm_pass(sb + 16384, sb + 32768, rta, rtb, khA16, khB16, sw, acc); // lh
        if (lane == 0) mbar_arrive(bempty[s]);
        if (t == 0 && c + 2 < nc) {
            mbar_wait(bempty[s], eph[s]); eph[s] ^= 1;
            issue(c + 2);
        }
    }

    // epilogue
    const int row0 = bm + wm * 32 + (lane >> 2);
    const int col0 = bn + wn * 64 + (lane & 3) * 2;
    #pragma unroll
    for (int mi = 0; mi < 2; mi++) {
        #pragma unroll
        for (int ni = 0; ni < 8; ni++) {
            const int col = col0 + ni * 8;
            float bb0 = 0.f, bb1 = 0.f;
            if (EPI != EPI_HALF) { bb0 = bias[col]; bb1 = bias[col + 1]; }
            #pragma unroll
            for (int half = 0; half < 2; half++) {
                const int row = row0 + mi * 16 + half * 8;
                if (row < M) {
                    float v0 = acc[mi][ni][half * 2]     + bb0;
                    float v1 = acc[mi][ni][half * 2 + 1] + bb1;
                    if (EPI == EPI_HALF) {
                        __half2 h2 = __floats2half2_rn(acc[mi][ni][half * 2],
                                                       acc[mi][ni][half * 2 + 1]);
                        *(uint32_t*)(Ch + (size_t)row * N + col) = *(uint32_t*)&h2;
                    } else if (EPI == EPI_BIAS_GELU_SPLIT) {
                        v0 = 0.5f * v0 * (1.0f + erff(v0 * 0.70710678118654752f));
                        v1 = 0.5f * v1 * (1.0f + erff(v1 * 0.70710678118654752f));
                        uint32_t hi, lo;
                        split_pair(v0, v1, hi, lo);
                        size_t base = ((size_t)(col >> 6) * MPAD + row) * 128
                                    + ((uint32_t)(2 * (col & 63)) ^ (uint32_t)((row & 7) << 4));
                        *(uint32_t*)(Sh + base) = hi;
                        *(uint32_t*)(Sl + base) = lo;
                    } else { // EPI_BIAS_RES
                        const float2 r2 = *(const float2*)(res + (size_t)row * N + col);
                        *(float2*)(C + (size_t)row * N + col) =
                            make_float2(v0 + r2.x, v1 + r2.y);
                    }
                }
            }
        }
    }
}

// ---------------------------------------------------------------------------
// fp16 tensor-core flash attention.
// grid (10, B*H), 128 threads (4 warps; warp w owns Q rows w*16..w*16+15).
// Q/K/V tiles 64x64 fp16 in swizzled smem. Epilogue writes bf16 hi/lo split
// (pair A) for the proj GEMM.
// ---------------------------------------------------------------------------
__global__ __launch_bounds__(128) void attn_ker(const __half* __restrict__ qkv,
                                                uint8_t* __restrict__ oh,
                                                uint8_t* __restrict__ ol)
{
    const int bh = blockIdx.y;
    const int b  = bh / NHEAD;
    const int h  = bh % NHEAD;
    const int q0 = blockIdx.x * 64;
    const int t  = threadIdx.x, lane = t & 31, w = t >> 5;

    __shared__ __align__(16) uint8_t qs[64 * 128];
    __shared__ __align__(16) uint8_t ks[64 * 128];
    __shared__ __align__(16) uint8_t vs[64 * 128];
    const uint32_t qsa = cvta_s(qs), ksa = cvta_s(ks), vsa = cvta_s(vs);

    // load Q tile (fp16 source, 8B stores)
    for (int idx = t; idx < 1024; idx += 128) {
        const int r = idx >> 4, g = idx & 15;
        const int qr = q0 + r;
        uint2 val = make_uint2(0u, 0u);
        if (qr < SEQ)
            val = *(const uint2*)(qkv + (size_t)(b * SEQ + qr) * C_QKV + h * HDIM + g * 4);
        *(uint2*)(qs + r * 128 + ((g * 8) ^ ((r & 7) << 4))) = val;
    }
    __syncthreads();

    const uint32_t swl = (uint32_t)(lane & 7) << 4;
    const uint32_t nt  = (uint32_t)(lane >> 4);
    const uint32_t rhalf = (uint32_t)((lane >> 3) & 1);
    const uint32_t khA = nt * 16;
    const uint32_t khB = rhalf * 16;

    // Q A-fragments (loop invariant)
    uint32_t qa[4][4];
    {
        const uint32_t rowA = (uint32_t)(w * 16 + rhalf * 8 + (lane & 7)) * 128;
        #pragma unroll
        for (int kc = 0; kc < 4; kc++)
            ldsm4(qa[kc], qsa + rowA + (((uint32_t)(kc * 32) + khA) ^ swl));
    }

    float m0 = -1e30f, m1 = -1e30f, l0 = 0.f, l1 = 0.f;
    float o[8][4];
    #pragma unroll
    for (int nj = 0; nj < 8; nj++)
        #pragma unroll
        for (int r = 0; r < 4; r++) o[nj][r] = 0.f;

    const int c0 = (lane & 3) * 2;

    for (int j0 = 0; j0 < SEQ; j0 += 64) {
        // load K,V tiles
        for (int idx = t; idx < 1024; idx += 128) {
            const int r = idx >> 4, g = idx & 15;
            const int kr = j0 + r;
            uint2 kvv = make_uint2(0u, 0u), vvv = make_uint2(0u, 0u);
            if (kr < SEQ) {
                const size_t base = (size_t)(b * SEQ + kr) * C_QKV + h * HDIM + g * 4;
                kvv = *(const uint2*)(qkv + base + C_EMB);
                vvv = *(const uint2*)(qkv + base + 2 * C_EMB);
            }
            const uint32_t off = r * 128 + ((g * 8) ^ ((r & 7) << 4));
            *(uint2*)(ks + off) = kvv;
            *(uint2*)(vs + off) = vvv;
        }
        __syncthreads();

        // S = Q K^T
        float s[8][4];
        #pragma unroll
        for (int nj = 0; nj < 8; nj++)
            #pragma unroll
            for (int r = 0; r < 4; r++) s[nj][r] = 0.f;
        #pragma unroll
        for (int kc = 0; kc < 4; kc++) {
            #pragma unroll
            for (int j = 0; j < 4; j++) {
                uint32_t bb[4];
                const uint32_t row = (uint32_t)((2 * j + nt) * 8 + (lane & 7)) * 128;
                ldsm4(bb, ksa + row + (((uint32_t)(kc * 32) + khB) ^ swl));
                mma_f16(s[2 * j],     qa[kc], &bb[0]);
                mma_f16(s[2 * j + 1], qa[kc], &bb[2]);
            }
        }

        // scale + mask
        #pragma unroll
        for (int nj = 0; nj < 8; nj++) {
            const int col = j0 + nj * 8 + c0;
            const bool ok0 = col < SEQ, ok1 = (col + 1) < SEQ;
            s[nj][0] = ok0 ? s[nj][0] * 0.125f : -1e30f;
            s[nj][1] = ok1 ? s[nj][1] * 0.125f : -1e30f;
            s[nj][2] = ok0 ? s[nj][2] * 0.125f : -1e30f;
            s[nj][3] = ok1 ? s[nj][3] * 0.125f : -1e30f;
        }

        // online softmax (rows r and r+8 per thread; quad-lane reduction)
        float mx0 = -1e30f, mx1 = -1e30f;
        #pragma unroll
        for (int nj = 0; nj < 8; nj++) {
            mx0 = fmaxf(mx0, fmaxf(s[nj][0], s[nj][1]));
            mx1 = fmaxf(mx1, fmaxf(s[nj][2], s[nj][3]));
        }
        mx0 = fmaxf(mx0, __shfl_xor_sync(0xFFFFFFFFu, mx0, 1));
        mx0 = fmaxf(mx0, __shfl_xor_sync(0xFFFFFFFFu, mx0, 2));
        mx1 = fmaxf(mx1, __shfl_xor_sync(0xFFFFFFFFu, mx1, 1));
        mx1 = fmaxf(mx1, __shfl_xor_sync(0xFFFFFFFFu, mx1, 2));
        const float nm0 = fmaxf(m0, mx0), nm1 = fmaxf(m1, mx1);
        const float cr0 = __expf(m0 - nm0), cr1 = __expf(m1 - nm1);
        m0 = nm0; m1 = nm1;
        float rs0 = 0.f, rs1 = 0.f;
        #pragma unroll
        for (int nj = 0; nj < 8; nj++) {
            float p0 = __expf(s[nj][0] - m0);
            float p1 = __expf(s[nj][1] - m0);
            float p2 = __expf(s[nj][2] - m1);
            float p3 = __expf(s[nj][3] - m1);
            s[nj][0] = p0; s[nj][1] = p1; s[nj][2] = p2; s[nj][3] = p3;
            rs0 += p0 + p1;
            rs1 += p2 + p3;
        }
        rs0 += __shfl_xor_sync(0xFFFFFFFFu, rs0, 1);
        rs0 += __shfl_xor_sync(0xFFFFFFFFu, rs0, 2);
        rs1 += __shfl_xor_sync(0xFFFFFFFFu, rs1, 1);
        rs1 += __shfl_xor_sync(0xFFFFFFFFu, rs1, 2);
        l0 = l0 * cr0 + rs0;
        l1 = l1 * cr1 + rs1;
        #pragma unroll
        for (int nj = 0; nj < 8; nj++) {
            o[nj][0] *= cr0; o[nj][1] *= cr0;
            o[nj][2] *= cr1; o[nj][3] *= cr1;
        }

        // O += P V  (P repacked to fp16 A-frags, V via ldmatrix.trans)
        #pragma unroll
        for (int kc = 0; kc < 4; kc++) {
            uint32_t pa[4];
            {
                __half2 t0 = __floats2half2_rn(s[2 * kc][0],     s[2 * kc][1]);
                __half2 t1 = __floats2half2_rn(s[2 * kc][2],     s[2 * kc][3]);
                __half2 t2 = __floats2half2_rn(s[2 * kc + 1][0], s[2 * kc + 1][1]);
                __half2 t3 = __floats2half2_rn(s[2 * kc + 1][2], s[2 * kc + 1][3]);
                pa[0] = *(uint32_t*)&t0; pa[1] = *(uint32_t*)&t1;
                pa[2] = *(uint32_t*)&t2; pa[3] = *(uint32_t*)&t3;
            }
            const uint32_t row = (uint32_t)(kc * 16 + rhalf * 8 + (lane & 7)) * 128;
            #pragma unroll
            for (int j = 0; j < 4; j++) {
                uint32_t vb[4];
                const uint32_t colb = 16u * (uint32_t)(2 * j + nt);
                ldsm4t(vb, vsa + row + (colb ^ swl));
                mma_f16(o[2 * j],     pa, &vb[0]);
                mma_f16(o[2 * j + 1], pa, &vb[2]);
            }
        }
        __syncthreads();
    }

    // epilogue: normalize + bf16 hi/lo split directly into pair A
    #pragma unroll
    for (int half = 0; half < 2; half++) {
        const int qr = q0 + w * 16 + (lane >> 2) + half * 8;
        if (qr < SEQ) {
            const float inv = 1.0f / (half ? l1 : l0);
            const size_t mtok = (size_t)b * SEQ + qr;
            const uint32_t swr = ((uint32_t)(mtok & 7)) << 4;
            const size_t rowbase = ((size_t)h * MPAD + mtok) * 128;
            #pragma unroll
            for (int nj = 0; nj < 8; nj++) {
                const int d = nj * 8 + c0;
                const float v0 = o[nj][half * 2]     * inv;
                const float v1 = o[nj][half * 2 + 1] * inv;
                uint32_t hi, lo;
                split_pair(v0, v1, hi, lo);
                const size_t off = rowbase + (((uint32_t)(2 * d)) ^ swr);
                *(uint32_t*)(oh + off) = hi;
                *(uint32_t*)(ol + off) = lo;
            }
        }
    }
}

// ---------------------------------------------------------------------------
// Launch
// ---------------------------------------------------------------------------
extern "C" void kernel_launch(void* const* d_in, const int* in_sizes, int n_in,
                              void* d_out, int out_size)
{
    const float* x      = (const float*)d_in[0];
    const float* ln1_g  = (const float*)d_in[1];
    const float* ln1_b  = (const float*)d_in[2];
    const float* w_qkv  = (const float*)d_in[3];
    const float* w_proj = (const float*)d_in[4];
    const float* b_proj = (const float*)d_in[5];
    const float* ln2_g  = (const float*)d_in[6];
    const float* ln2_b  = (const float*)d_in[7];
    const float* w_fc1  = (const float*)d_in[8];
    const float* b_fc1  = (const float*)d_in[9];
    const float* w_fc2  = (const float*)d_in[10];
    const float* b_fc2  = (const float*)d_in[11];
    float* out = (float*)d_out;

    __half* p_qkvh; float* p_x1;
    uint8_t *p_ah, *p_al, *p_bh, *p_bl, *p_wh, *p_wl;
    cudaGetSymbolAddress((void**)&p_qkvh, g_qkvh);
    cudaGetSymbolAddress((void**)&p_x1,   g_x1);
    cudaGetSymbolAddress((void**)&p_ah,   g_ah);
    cudaGetSymbolAddress((void**)&p_al,   g_al);
    cudaGetSymbolAddress((void**)&p_bh,   g_bh);
    cudaGetSymbolAddress((void**)&p_bl,   g_bl);
    cudaGetSymbolAddress((void**)&p_wh,   g_wh);
    cudaGetSymbolAddress((void**)&p_wl,   g_wl);

    cudaFuncSetAttribute(gemm_mma_ker<EPI_BIAS_RES>,
                         cudaFuncAttributeMaxDynamicSharedMemorySize, GEMM_SMEM);
    cudaFuncSetAttribute(gemm_mma_ker<EPI_BIAS_GELU_SPLIT>,
                         cudaFuncAttributeMaxDynamicSharedMemorySize, GEMM_SMEM);
    cudaFuncSetAttribute(gemm_mma_ker<EPI_HALF>,
                         cudaFuncAttributeMaxDynamicSharedMemorySize, GEMM_SMEM);

    const int M = MTOK;
    const int MY = (M + 127) / 128;   // 289
    const dim3 blkT(32, 4);

    // 1) LN1 + split -> pair A
    ln_split_ker<<<M, 256>>>(x, ln1_g, ln1_b, p_ah, p_al);
    // 2) split+transpose w_qkv
    splitT_ker<<<dim3(C_QKV / 32, C_EMB / 32), blkT>>>(w_qkv, p_wh, p_wl, C_EMB, C_QKV);
    // 3) qkv GEMM -> fp16
    gemm_mma_ker<EPI_HALF><<<dim3(C_QKV / 128, MY), 256, GEMM_SMEM>>>(
        p_ah, p_al, p_wh, p_wl, nullptr, nullptr,
        nullptr, p_qkvh, nullptr, nullptr, M, C_QKV, C_EMB);
    // 4) fp16 flash attention -> split pair A
    attn_ker<<<dim3((SEQ + 63) / 64, BATCH * NHEAD), 128>>>(p_qkvh, p_ah, p_al);
    // 5) w_proj split
    splitT_ker<<<dim3(C_EMB / 32, C_EMB / 32), blkT>>>(w_proj, p_wh, p_wl, C_EMB, C_EMB);
    // 6) x1 = x + att @ w_proj + b_proj
    gemm_mma_ker<EPI_BIAS_RES><<<dim3(C_EMB / 128, MY), 256, GEMM_SMEM>>>(
        p_ah, p_al, p_wh, p_wl, b_proj, x,
        p_x1, nullptr, nullptr, nullptr, M, C_EMB, C_EMB);
    // 7) LN2 + split -> pair A
    ln_split_ker<<<M, 256>>>(p_x1, ln2_g, ln2_b, p_ah, p_al);
    // 8) w_fc1 split
    splitT_ker<<<dim3(C_HID / 32, C_EMB / 32), blkT>>>(w_fc1, p_wh, p_wl, C_EMB, C_HID);
    // 9) ff = gelu(h @ w_fc1 + b_fc1) -> split pair B
    gemm_mma_ker<EPI_BIAS_GELU_SPLIT><<<dim3(C_HID / 128, MY), 256, GEMM_SMEM>>>(
        p_ah, p_al, p_wh, p_wl, b_fc1, nullptr,
        nullptr, nullptr, p_bh, p_bl, M, C_HID, C_EMB);
    // 10) w_fc2 split
    splitT_ker<<<dim3(C_EMB / 32, C_HID / 32), blkT>>>(w_fc2, p_wh, p_wl, C_HID, C_EMB);
    // 11) out = x1 + ff @ w_fc2 + b_fc2
    gemm_mma_ker<EPI_BIAS_RES><<<dim3(C_EMB / 128, MY), 256, GEMM_SMEM>>>(
        p_bh, p_bl, p_wh, p_wl, b_fc2, p_x1,
        out, nullptr, nullptr, nullptr, M, C_EMB, C_HID);
}

// round 6
// speedup vs baseline: 3.8110x; 1.0004x over previous
#include <cuda_runtime.h>
#include <cuda_bf16.h>
#include <cuda_fp16.h>
#include <math.h>
#include <stdint.h>

// ---------------------------------------------------------------------------
// Problem constants
// ---------------------------------------------------------------------------
#define BATCH   64
#define SEQ     577
#define MTOK    (BATCH * SEQ)      // 36928
#define MPAD    36992              // 289 * 128
#define C_EMB   768
#define C_QKV   2304
#define C_HID   3072
#define NHEAD   12
#define HDIM    64

#define EPI_BIAS_RES        1
#define EPI_BIAS_GELU_SPLIT 2
#define EPI_HALF            3

// ---------------------------------------------------------------------------
// Scratch (device globals)
// ---------------------------------------------------------------------------
__device__ __half g_qkvh[(size_t)MTOK * C_QKV];            // qkv proj, fp16
__device__ float  g_x1 [(size_t)MTOK * C_EMB];             // residual 1
// split activation operands, chunked+swizzled: [K/64][MPAD rows][64 bf16]
__device__ __nv_bfloat16 g_ah[(size_t)MPAD * C_EMB];       // pair A (K=768 acts)
__device__ __nv_bfloat16 g_al[(size_t)MPAD * C_EMB];
__device__ __nv_bfloat16 g_bh[(size_t)MPAD * C_HID];       // pair B (ff acts)
__device__ __nv_bfloat16 g_bl[(size_t)MPAD * C_HID];
// split weights, chunked+swizzled: [K/64][N][64 bf16]
__device__ __nv_bfloat16 g_wh[(size_t)C_HID * C_EMB];
__device__ __nv_bfloat16 g_wl[(size_t)C_HID * C_EMB];

// ---------------------------------------------------------------------------
// PTX helpers
// ---------------------------------------------------------------------------
__device__ __forceinline__ uint32_t cvta_s(const void* p) {
    uint32_t a;
    asm("{ .reg .u64 t; cvta.to.shared.u64 t, %1; cvt.u32.u64 %0, t; }"
        : "=r"(a) : "l"(p));
    return a;
}
__device__ __forceinline__ void mbar_init(uint32_t mbar, uint32_t cnt) {
    asm volatile("mbarrier.init.shared.b64 [%0], %1;" :: "r"(mbar), "r"(cnt) : "memory");
}
__device__ __forceinline__ void mbar_expect_tx(uint32_t mbar, uint32_t bytes) {
    asm volatile("mbarrier.arrive.expect_tx.shared.b64 _, [%0], %1;"
                 :: "r"(mbar), "r"(bytes) : "memory");
}
__device__ __forceinline__ void mbar_arrive(uint32_t mbar) {
    asm volatile("mbarrier.arrive.shared.b64 _, [%0];" :: "r"(mbar) : "memory");
}
__device__ __forceinline__ void mbar_wait(uint32_t mbar, uint32_t phase) {
    asm volatile(
        "{\n\t"
        ".reg .pred P1;\n\t"
        "WAIT_LOOP_%=:\n\t"
        "mbarrier.try_wait.parity.acquire.cta.shared::cta.b64 P1, [%0], %1, 0x989680;\n\t"
        "@P1 bra.uni WAIT_DONE_%=;\n\t"
        "bra.uni WAIT_LOOP_%=;\n\t"
        "WAIT_DONE_%=:\n\t"
        "}"
        :: "r"(mbar), "r"(phase) : "memory");
}
__device__ __forceinline__ void bulk_ldg(uint32_t dst, const void* src,
                                         uint32_t bytes, uint32_t mbar) {
    asm volatile(
        "cp.async.bulk.shared::cluster.global.mbarrier::complete_tx::bytes "
        "[%0], [%1], %2, [%3];"
        :: "r"(dst), "l"(src), "r"(bytes), "r"(mbar) : "memory");
}
__device__ __forceinline__ void ldsm4(uint32_t* r, uint32_t addr) {
    asm volatile("ldmatrix.sync.aligned.m8n8.x4.shared.b16 {%0,%1,%2,%3}, [%4];"
                 : "=r"(r[0]), "=r"(r[1]), "=r"(r[2]), "=r"(r[3]) : "r"(addr));
}
__device__ __forceinline__ void ldsm4t(uint32_t* r, uint32_t addr) {
    asm volatile("ldmatrix.sync.aligned.m8n8.x4.trans.shared.b16 {%0,%1,%2,%3}, [%4];"
                 : "=r"(r[0]), "=r"(r[1]), "=r"(r[2]), "=r"(r[3]) : "r"(addr));
}
__device__ __forceinline__ void mma_bf16(float* c, const uint32_t* a, const uint32_t* b) {
    asm volatile(
        "mma.sync.aligned.m16n8k16.row.col.f32.bf16.bf16.f32 "
        "{%0,%1,%2,%3},{%4,%5,%6,%7},{%8,%9},{%0,%1,%2,%3};"
        : "+f"(c[0]), "+f"(c[1]), "+f"(c[2]), "+f"(c[3])
        : "r"(a[0]), "r"(a[1]), "r"(a[2]), "r"(a[3]), "r"(b[0]), "r"(b[1]));
}
__device__ __forceinline__ void mma_f16(float* c, const uint32_t* a, const uint32_t* b) {
    asm volatile(
        "mma.sync.aligned.m16n8k16.row.col.f32.f16.f16.f32 "
        "{%0,%1,%2,%3},{%4,%5,%6,%7},{%8,%9},{%0,%1,%2,%3};"
        : "+f"(c[0]), "+f"(c[1]), "+f"(c[2]), "+f"(c[3])
        : "r"(a[0]), "r"(a[1]), "r"(a[2]), "r"(a[3]), "r"(b[0]), "r"(b[1]));
}

__device__ __forceinline__ uint32_t pack_bf2(float a, float b) {
    __nv_bfloat162 r = __floats2bfloat162_rn(a, b);
    return *(uint32_t*)&r;
}
__device__ __forceinline__ void split_pair(float v0, float v1, uint32_t& hi, uint32_t& lo) {
    __nv_bfloat16 h0 = __float2bfloat16(v0);
    __nv_bfloat16 h1 = __float2bfloat16(v1);
    __nv_bfloat162 hh; hh.x = h0; hh.y = h1;
    hi = *(uint32_t*)&hh;
    lo = pack_bf2(v0 - __bfloat162float(h0), v1 - __bfloat162float(h1));
}

// ---------------------------------------------------------------------------
// Fused LayerNorm + bf16 hi/lo split (K=768) -> pair A chunked swizzled
// ---------------------------------------------------------------------------
__global__ __launch_bounds__(256) void ln_split_ker(const float* __restrict__ x,
                                                    const float* __restrict__ gamma,
                                                    const float* __restrict__ beta,
                                                    uint8_t* __restrict__ hi,
                                                    uint8_t* __restrict__ lo)
{
    const int row = blockIdx.x;
    const float* xr = x + (size_t)row * C_EMB;
    float s = 0.f, s2 = 0.f;
    #pragma unroll
    for (int c = threadIdx.x; c < C_EMB; c += 256) {
        float v = xr[c];
        s += v; s2 += v * v;
    }
    #pragma unroll
    for (int off = 16; off > 0; off >>= 1) {
        s  += __shfl_down_sync(0xFFFFFFFFu, s,  off);
        s2 += __shfl_down_sync(0xFFFFFFFFu, s2, off);
    }
    __shared__ float shs[8], shs2[8];
    const int lane = threadIdx.x & 31, warp = threadIdx.x >> 5;
    if (lane == 0) { shs[warp] = s; shs2[warp] = s2; }
    __syncthreads();
    if (threadIdx.x == 0) {
        float ts = 0.f, ts2 = 0.f;
        #pragma unroll
        for (int w = 0; w < 8; w++) { ts += shs[w]; ts2 += shs2[w]; }
        float mean = ts * (1.0f / C_EMB);
        float var  = ts2 * (1.0f / C_EMB) - mean * mean;
        shs[0]  = mean;
        shs2[0] = rsqrtf(var + 1e-5f);
    }
    __syncthreads();
    const float mean = shs[0], rstd = shs2[0];
    if (threadIdx.x < 96) {
        const int k = threadIdx.x * 8;
        union { __nv_bfloat16 b[8]; uint4 u; } uh, ul;
        #pragma unroll
        for (int i = 0; i < 8; i++) {
            float v = (xr[k + i] - mean) * rstd * gamma[k + i] + beta[k + i];
            __nv_bfloat16 h = __float2bfloat16(v);
            uh.b[i] = h;
            ul.b[i] = __float2bfloat16(v - __bfloat162float(h));
        }
        size_t base = ((size_t)(k >> 6) * MPAD + row) * 128
                    + ((uint32_t)((k & 63) * 2) ^ (uint32_t)((row & 7) << 4));
        *(uint4*)(hi + base) = uh.u;
        *(uint4*)(lo + base) = ul.u;
    }
}

// ---------------------------------------------------------------------------
// splitT: fp32 weights [K,N] -> transposed hi/lo bf16 chunked swizzled [K/64][N][64]
// ---------------------------------------------------------------------------
__global__ void splitT_ker(const float* __restrict__ w,
                           uint8_t* __restrict__ hi, uint8_t* __restrict__ lo,
                           int K, int N)
{
    __shared__ float tile[32][33];
    const int n0 = blockIdx.x * 32, k0 = blockIdx.y * 32;
    const int tx = threadIdx.x, ty = threadIdx.y;
    for (int i = ty; i < 32; i += 4)
        tile[i][tx] = w[(size_t)(k0 + i) * N + n0 + tx];
    __syncthreads();
    const int n = n0 + tx;
    const int k = k0 + ty * 8;
    union { __nv_bfloat16 b[8]; uint4 u; } uh, ul;
    #pragma unroll
    for (int i = 0; i < 8; i++) {
        float v = tile[ty * 8 + i][tx];
        __nv_bfloat16 h = __float2bfloat16(v);
        uh.b[i] = h;
        ul.b[i] = __float2bfloat16(v - __bfloat162float(h));
    }
    size_t base = ((size_t)(k >> 6) * N + n) * 128
                + ((uint32_t)((k & 63) * 2) ^ (uint32_t)((n & 7) << 4));
    *(uint4*)(hi + base) = uh.u;
    *(uint4*)(lo + base) = ul.u;
}

// ---------------------------------------------------------------------------
// bf16-split warp-MMA GEMM (hh+hl+lh), 2-stage cp.async.bulk pipeline.
// Epilogues: fp32+bias+res | bias+GELU+split-out | fp16-out
// ---------------------------------------------------------------------------
#define STAGE_BYTES 65536
#define GEMM_SMEM   (2 * STAGE_BYTES + 1024)

__device__ __forceinline__ void gemm_pass(uint32_t aB, uint32_t bB,
                                          const uint32_t rta[2], const uint32_t rtb[4],
                                          uint32_t khA16, uint32_t khB16, uint32_t sw,
                                          float (&acc)[2][8][4])
{
    #pragma unroll
    for (int ks = 0; ks < 4; ks++) {
        const uint32_t offA = (uint32_t)(ks * 32 + khA16) ^ sw;
        const uint32_t offB = (uint32_t)(ks * 32 + khB16) ^ sw;
        uint32_t a[2][4], b[4][4];
        ldsm4(a[0], aB + rta[0] + offA);
        ldsm4(a[1], aB + rta[1] + offA);
        #pragma unroll
        for (int j = 0; j < 4; j++)
            ldsm4(b[j], bB + rtb[j] + offB);
        #pragma unroll
        for (int mi = 0; mi < 2; mi++)
            #pragma unroll
            for (int j = 0; j < 4; j++) {
                mma_bf16(acc[mi][2 * j],     a[mi], &b[j][0]);
                mma_bf16(acc[mi][2 * j + 1], a[mi], &b[j][2]);
            }
    }
}

template<int EPI>
__global__ __launch_bounds__(256, 1) void gemm_mma_ker(
    const uint8_t* __restrict__ Ah, const uint8_t* __restrict__ Al,
    const uint8_t* __restrict__ Bh, const uint8_t* __restrict__ Bl,
    const float* __restrict__ bias, const float* __restrict__ res,
    float* __restrict__ C, __half* __restrict__ Ch,
    uint8_t* __restrict__ Sh, uint8_t* __restrict__ Sl,
    int M, int N, int K)
{
    extern __shared__ uint8_t dynsmem[];
    __shared__ __align__(8) uint64_t s_bar[4];

    const int t = threadIdx.x, lane = t & 31, wid = t >> 5;
    const int wm = wid >> 1, wn = wid & 1;
    const int bm = blockIdx.y * 128, bn = blockIdx.x * 128;

    const uint32_t sbase = (cvta_s(dynsmem) + 1023u) & ~1023u;
    uint32_t bfull[2]  = { cvta_s(&s_bar[0]), cvta_s(&s_bar[1]) };
    uint32_t bempty[2] = { cvta_s(&s_bar[2]), cvta_s(&s_bar[3]) };

    if (t == 0) {
        mbar_init(bfull[0], 1);  mbar_init(bfull[1], 1);
        mbar_init(bempty[0], 8); mbar_init(bempty[1], 8);
    }
    __syncthreads();

    const int nc = K >> 6;
    auto issue = [&](int c) {
        const int s = c & 1;
        const uint32_t sb = sbase + (uint32_t)s * STAGE_BYTES;
        mbar_expect_tx(bfull[s], STAGE_BYTES);
        bulk_ldg(sb,         Ah + ((size_t)c * MPAD + bm) * 128, 16384, bfull[s]);
        bulk_ldg(sb + 16384, Al + ((size_t)c * MPAD + bm) * 128, 16384, bfull[s]);
        bulk_ldg(sb + 32768, Bh + ((size_t)c * N + bn) * 128,    16384, bfull[s]);
        bulk_ldg(sb + 49152, Bl + ((size_t)c * N + bn) * 128,    16384, bfull[s]);
    };
    if (t == 0) { issue(0); if (nc > 1) issue(1); }

    const uint32_t sw = (uint32_t)(lane & 7) << 4;
    uint32_t rta[2], rtb[4];
    {
        const int rowoff = ((lane >> 3) & 1) * 8 + (lane & 7);
        rta[0] = (uint32_t)(wm * 32 +  0 + rowoff) * 128;
        rta[1] = (uint32_t)(wm * 32 + 16 + rowoff) * 128;
        const int nt = lane >> 4;
        #pragma unroll
        for (int j = 0; j < 4; j++)
            rtb[j] = (uint32_t)(wn * 64 + (2 * j + nt) * 8 + (lane & 7)) * 128;
    }
    const uint32_t khA16 = (uint32_t)(lane >> 4) * 16;
    const uint32_t khB16 = (uint32_t)((lane >> 3) & 1) * 16;

    float acc[2][8][4];
    #pragma unroll
    for (int mi = 0; mi < 2; mi++)
        #pragma unroll
        for (int ni = 0; ni < 8; ni++)
            #pragma unroll
            for (int r = 0; r < 4; r++) acc[mi][ni][r] = 0.f;

    int fph[2] = {0, 0}, eph[2] = {0, 0};
    for (int c = 0; c < nc; c++) {
        const int s = c & 1;
        mbar_wait(bfull[s], fph[s]); fph[s] ^= 1;
        const uint32_t sb = sbase + (uint32_t)s * STAGE_BYTES;
        gemm_pass(sb,         sb + 32768, rta, rtb, khA16, khB16, sw, acc); // hh
        gemm_pass(sb,         sb + 49152, rta, rtb, khA16, khB16, sw, acc); // hl
        gemm_pass(sb + 16384, sb + 32768, rta, rtb, khA16, khB16, sw, acc); // lh
        if (lane == 0) mbar_arrive(bempty[s]);
        if (t == 0 && c + 2 < nc) {
            mbar_wait(bempty[s], eph[s]); eph[s] ^= 1;
            issue(c + 2);
        }
    }

    // epilogue
    const int row0 = bm + wm * 32 + (lane >> 2);
    const int col0 = bn + wn * 64 + (lane & 3) * 2;
    #pragma unroll
    for (int mi = 0; mi < 2; mi++) {
        #pragma unroll
        for (int ni = 0; ni < 8; ni++) {
            const int col = col0 + ni * 8;
            float bb0 = 0.f, bb1 = 0.f;
            if (EPI != EPI_HALF) { bb0 = bias[col]; bb1 = bias[col + 1]; }
            #pragma unroll
            for (int half = 0; half < 2; half++) {
                const int row = row0 + mi * 16 + half * 8;
                if (row < M) {
                    float v0 = acc[mi][ni][half * 2]     + bb0;
                    float v1 = acc[mi][ni][half * 2 + 1] + bb1;
                    if (EPI == EPI_HALF) {
                        __half2 h2 = __floats2half2_rn(acc[mi][ni][half * 2],
                                                       acc[mi][ni][half * 2 + 1]);
                        *(uint32_t*)(Ch + (size_t)row * N + col) = *(uint32_t*)&h2;
                    } else if (EPI == EPI_BIAS_GELU_SPLIT) {
                        v0 = 0.5f * v0 * (1.0f + erff(v0 * 0.70710678118654752f));
                        v1 = 0.5f * v1 * (1.0f + erff(v1 * 0.70710678118654752f));
                        uint32_t hi, lo;
                        split_pair(v0, v1, hi, lo);
                        size_t base = ((size_t)(col >> 6) * MPAD + row) * 128
                                    + ((uint32_t)(2 * (col & 63)) ^ (uint32_t)((row & 7) << 4));
                        *(uint32_t*)(Sh + base) = hi;
                        *(uint32_t*)(Sl + base) = lo;
                    } else { // EPI_BIAS_RES
                        const float2 r2 = *(const float2*)(res + (size_t)row * N + col);
                        *(float2*)(C + (size_t)row * N + col) =
                            make_float2(v0 + r2.x, v1 + r2.y);
                    }
                }
            }
        }
    }
}

// ---------------------------------------------------------------------------
// fp16 tensor-core flash attention.
// grid (10, B*H), 128 threads (4 warps; warp w owns Q rows w*16..w*16+15).
// Q/K/V tiles 64x64 fp16 in swizzled smem. Epilogue writes bf16 hi/lo split
// (pair A) for the proj GEMM.
// ---------------------------------------------------------------------------
__global__ __launch_bounds__(128) void attn_ker(const __half* __restrict__ qkv,
                                                uint8_t* __restrict__ oh,
                                                uint8_t* __restrict__ ol)
{
    const int bh = blockIdx.y;
    const int b  = bh / NHEAD;
    const int h  = bh % NHEAD;
    const int q0 = blockIdx.x * 64;
    const int t  = threadIdx.x, lane = t & 31, w = t >> 5;

    __shared__ __align__(16) uint8_t qs[64 * 128];
    __shared__ __align__(16) uint8_t ks[64 * 128];
    __shared__ __align__(16) uint8_t vs[64 * 128];
    const uint32_t qsa = cvta_s(qs), ksa = cvta_s(ks), vsa = cvta_s(vs);

    // load Q tile (fp16 source, 8B stores)
    for (int idx = t; idx < 1024; idx += 128) {
        const int r = idx >> 4, g = idx & 15;
        const int qr = q0 + r;
        uint2 val = make_uint2(0u, 0u);
        if (qr < SEQ)
            val = *(const uint2*)(qkv + (size_t)(b * SEQ + qr) * C_QKV + h * HDIM + g * 4);
        *(uint2*)(qs + r * 128 + ((g * 8) ^ ((r & 7) << 4))) = val;
    }
    __syncthreads();

    const uint32_t swl = (uint32_t)(lane & 7) << 4;
    const uint32_t nt  = (uint32_t)(lane >> 4);
    const uint32_t rhalf = (uint32_t)((lane >> 3) & 1);
    const uint32_t khA = nt * 16;
    const uint32_t khB = rhalf * 16;

    // Q A-fragments (loop invariant)
    uint32_t qa[4][4];
    {
        const uint32_t rowA = (uint32_t)(w * 16 + rhalf * 8 + (lane & 7)) * 128;
        #pragma unroll
        for (int kc = 0; kc < 4; kc++)
            ldsm4(qa[kc], qsa + rowA + (((uint32_t)(kc * 32) + khA) ^ swl));
    }

    float m0 = -1e30f, m1 = -1e30f, l0 = 0.f, l1 = 0.f;
    float o[8][4];
    #pragma unroll
    for (int nj = 0; nj < 8; nj++)
        #pragma unroll
        for (int r = 0; r < 4; r++) o[nj][r] = 0.f;

    const int c0 = (lane & 3) * 2;

    for (int j0 = 0; j0 < SEQ; j0 += 64) {
        // load K,V tiles
        for (int idx = t; idx < 1024; idx += 128) {
            const int r = idx >> 4, g = idx & 15;
            const int kr = j0 + r;
            uint2 kvv = make_uint2(0u, 0u), vvv = make_uint2(0u, 0u);
            if (kr < SEQ) {
                const size_t base = (size_t)(b * SEQ + kr) * C_QKV + h * HDIM + g * 4;
                kvv = *(const uint2*)(qkv + base + C_EMB);
                vvv = *(const uint2*)(qkv + base + 2 * C_EMB);
            }
            const uint32_t off = r * 128 + ((g * 8) ^ ((r & 7) << 4));
            *(uint2*)(ks + off) = kvv;
            *(uint2*)(vs + off) = vvv;
        }
        __syncthreads();

        // S = Q K^T
        float s[8][4];
        #pragma unroll
        for (int nj = 0; nj < 8; nj++)
            #pragma unroll
            for (int r = 0; r < 4; r++) s[nj][r] = 0.f;
        #pragma unroll
        for (int kc = 0; kc < 4; kc++) {
            #pragma unroll
            for (int j = 0; j < 4; j++) {
                uint32_t bb[4];
                const uint32_t row = (uint32_t)((2 * j + nt) * 8 + (lane & 7)) * 128;
                ldsm4(bb, ksa + row + (((uint32_t)(kc * 32) + khB) ^ swl));
                mma_f16(s[2 * j],     qa[kc], &bb[0]);
                mma_f16(s[2 * j + 1], qa[kc], &bb[2]);
            }
        }

        // scale + mask
        #pragma unroll
        for (int nj = 0; nj < 8; nj++) {
            const int col = j0 + nj * 8 + c0;
            const bool ok0 = col < SEQ, ok1 = (col + 1) < SEQ;
            s[nj][0] = ok0 ? s[nj][0] * 0.125f : -1e30f;
            s[nj][1] = ok1 ? s[nj][1] * 0.125f : -1e30f;
            s[nj][2] = ok0 ? s[nj][2] * 0.125f : -1e30f;
            s[nj][3] = ok1 ? s[nj][3] * 0.125f : -1e30f;
        }

        // online softmax (rows r and r+8 per thread; quad-lane reduction)
        float mx0 = -1e30f, mx1 = -1e30f;
        #pragma unroll
        for (int nj = 0; nj < 8; nj++) {
            mx0 = fmaxf(mx0, fmaxf(s[nj][0], s[nj][1]));
            mx1 = fmaxf(mx1, fmaxf(s[nj][2], s[nj][3]));
        }
        mx0 = fmaxf(mx0, __shfl_xor_sync(0xFFFFFFFFu, mx0, 1));
        mx0 = fmaxf(mx0, __shfl_xor_sync(0xFFFFFFFFu, mx0, 2));
        mx1 = fmaxf(mx1, __shfl_xor_sync(0xFFFFFFFFu, mx1, 1));
        mx1 = fmaxf(mx1, __shfl_xor_sync(0xFFFFFFFFu, mx1, 2));
        const float nm0 = fmaxf(m0, mx0), nm1 = fmaxf(m1, mx1);
        const float cr0 = __expf(m0 - nm0), cr1 = __expf(m1 - nm1);
        m0 = nm0; m1 = nm1;
        float rs0 = 0.f, rs1 = 0.f;
        #pragma unroll
        for (int nj = 0; nj < 8; nj++) {
            float p0 = __expf(s[nj][0] - m0);
            float p1 = __expf(s[nj][1] - m0);
            float p2 = __expf(s[nj][2] - m1);
            float p3 = __expf(s[nj][3] - m1);
            s[nj][0] = p0; s[nj][1] = p1; s[nj][2] = p2; s[nj][3] = p3;
            rs0 += p0 + p1;
            rs1 += p2 + p3;
        }
        rs0 += __shfl_xor_sync(0xFFFFFFFFu, rs0, 1);
        rs0 += __shfl_xor_sync(0xFFFFFFFFu, rs0, 2);
        rs1 += __shfl_xor_sync(0xFFFFFFFFu, rs1, 1);
        rs1 += __shfl_xor_sync(0xFFFFFFFFu, rs1, 2);
        l0 = l0 * cr0 + rs0;
        l1 = l1 * cr1 + rs1;
        #pragma unroll
        for (int nj = 0; nj < 8; nj++) {
            o[nj][0] *= cr0; o[nj][1] *= cr0;
            o[nj][2] *= cr1; o[nj][3] *= cr1;
        }

        // O += P V  (P repacked to fp16 A-frags, V via ldmatrix.trans)
        #pragma unroll
        for (int kc = 0; kc < 4; kc++) {
            uint32_t pa[4];
            {
                __half2 t0 = __floats2half2_rn(s[2 * kc][0],     s[2 * kc][1]);
                __half2 t1 = __floats2half2_rn(s[2 * kc][2],     s[2 * kc][3]);
                __half2 t2 = __floats2half2_rn(s[2 * kc + 1][0], s[2 * kc + 1][1]);
                __half2 t3 = __floats2half2_rn(s[2 * kc + 1][2], s[2 * kc + 1][3]);
                pa[0] = *(uint32_t*)&t0; pa[1] = *(uint32_t*)&t1;
                pa[2] = *(uint32_t*)&t2; pa[3] = *(uint32_t*)&t3;
            }
            const uint32_t row = (uint32_t)(kc * 16 + rhalf * 8 + (lane & 7)) * 128;
            #pragma unroll
            for (int j = 0; j < 4; j++) {
                uint32_t vb[4];
                const uint32_t colb = 16u * (uint32_t)(2 * j + nt);
                ldsm4t(vb, vsa + row + (colb ^ swl));
                mma_f16(o[2 * j],     pa, &vb[0]);
                mma_f16(o[2 * j + 1], pa, &vb[2]);
            }
        }
        __syncthreads();
    }

    // epilogue: normalize + bf16 hi/lo split directly into pair A
    #pragma unroll
    for (int half = 0; half < 2; half++) {
        const int qr = q0 + w * 16 + (lane >> 2) + half * 8;
        if (qr < SEQ) {
            const float inv = 1.0f / (half ? l1 : l0);
            const size_t mtok = (size_t)b * SEQ + qr;
            const uint32_t swr = ((uint32_t)(mtok & 7)) << 4;
            const size_t rowbase = ((size_t)h * MPAD + mtok) * 128;
            #pragma unroll
            for (int nj = 0; nj < 8; nj++) {
                const int d = nj * 8 + c0;
                const float v0 = o[nj][half * 2]     * inv;
                const float v1 = o[nj][half * 2 + 1] * inv;
                uint32_t hi, lo;
                split_pair(v0, v1, hi, lo);
                const size_t off = rowbase + (((uint32_t)(2 * d)) ^ swr);
                *(uint32_t*)(oh + off) = hi;
                *(uint32_t*)(ol + off) = lo;
            }
        }
    }
}

// ---------------------------------------------------------------------------
// Launch
// ---------------------------------------------------------------------------
extern "C" void kernel_launch(void* const* d_in, const int* in_sizes, int n_in,
                              void* d_out, int out_size)
{
    const float* x      = (const float*)d_in[0];
    const float* ln1_g  = (const float*)d_in[1];
    const float* ln1_b  = (const float*)d_in[2];
    const float* w_qkv  = (const float*)d_in[3];
    const float* w_proj = (const float*)d_in[4];
    const float* b_proj = (const float*)d_in[5];
    const float* ln2_g  = (const float*)d_in[6];
    const float* ln2_b  = (const float*)d_in[7];
    const float* w_fc1  = (const float*)d_in[8];
    const float* b_fc1  = (const float*)d_in[9];
    const float* w_fc2  = (const float*)d_in[10];
    const float* b_fc2  = (const float*)d_in[11];
    float* out = (float*)d_out;

    __half* p_qkvh; float* p_x1;
    uint8_t *p_ah, *p_al, *p_bh, *p_bl, *p_wh, *p_wl;
    cudaGetSymbolAddress((void**)&p_qkvh, g_qkvh);
    cudaGetSymbolAddress((void**)&p_x1,   g_x1);
    cudaGetSymbolAddress((void**)&p_ah,   g_ah);
    cudaGetSymbolAddress((void**)&p_al,   g_al);
    cudaGetSymbolAddress((void**)&p_bh,   g_bh);
    cudaGetSymbolAddress((void**)&p_bl,   g_bl);
    cudaGetSymbolAddress((void**)&p_wh,   g_wh);
    cudaGetSymbolAddress((void**)&p_wl,   g_wl);

    cudaFuncSetAttribute(gemm_mma_ker<EPI_BIAS_RES>,
                         cudaFuncAttributeMaxDynamicSharedMemorySize, GEMM_SMEM);
    cudaFuncSetAttribute(gemm_mma_ker<EPI_BIAS_GELU_SPLIT>,
                         cudaFuncAttributeMaxDynamicSharedMemorySize, GEMM_SMEM);
    cudaFuncSetAttribute(gemm_mma_ker<EPI_HALF>,
                         cudaFuncAttributeMaxDynamicSharedMemorySize, GEMM_SMEM);

    const int M = MTOK;
    const int MY = (M + 127) / 128;   // 289
    const dim3 blkT(32, 4);

    // 1) LN1 + split -> pair A
    ln_split_ker<<<M, 256>>>(x, ln1_g, ln1_b, p_ah, p_al);
    // 2) split+transpose w_qkv
    splitT_ker<<<dim3(C_QKV / 32, C_EMB / 32), blkT>>>(w_qkv, p_wh, p_wl, C_EMB, C_QKV);
    // 3) qkv GEMM -> fp16
    gemm_mma_ker<EPI_HALF><<<dim3(C_QKV / 128, MY), 256, GEMM_SMEM>>>(
        p_ah, p_al, p_wh, p_wl, nullptr, nullptr,
        nullptr, p_qkvh, nullptr, nullptr, M, C_QKV, C_EMB);
    // 4) fp16 flash attention -> split pair A
    attn_ker<<<dim3((SEQ + 63) / 64, BATCH * NHEAD), 128>>>(p_qkvh, p_ah, p_al);
    // 5) w_proj split
    splitT_ker<<<dim3(C_EMB / 32, C_EMB / 32), blkT>>>(w_proj, p_wh, p_wl, C_EMB, C_EMB);
    // 6) x1 = x + att @ w_proj + b_proj
    gemm_mma_ker<EPI_BIAS_RES><<<dim3(C_EMB / 128, MY), 256, GEMM_SMEM>>>(
        p_ah, p_al, p_wh, p_wl, b_proj, x,
        p_x1, nullptr, nullptr, nullptr, M, C_EMB, C_EMB);
    // 7) LN2 + split -> pair A
    ln_split_ker<<<M, 256>>>(p_x1, ln2_g, ln2_b, p_ah, p_al);
    // 8) w_fc1 split
    splitT_ker<<<dim3(C_HID / 32, C_EMB / 32), blkT>>>(w_fc1, p_wh, p_wl, C_EMB, C_HID);
    // 9) ff = gelu(h @ w_fc1 + b_fc1) -> split pair B
    gemm_mma_ker<EPI_BIAS_GELU_SPLIT><<<dim3(C_HID / 128, MY), 256, GEMM_SMEM>>>(
        p_ah, p_al, p_wh, p_wl, b_fc1, nullptr,
        nullptr, nullptr, p_bh, p_bl, M, C_HID, C_EMB);
    // 10) w_fc2 split
    splitT_ker<<<dim3(C_EMB / 32, C_HID / 32), blkT>>>(w_fc2, p_wh, p_wl, C_HID, C_EMB);
    // 11) out = x1 + ff @ w_fc2 + b_fc2
    gemm_mma_ker<EPI_BIAS_RES><<<dim3(C_EMB / 128, MY), 256, GEMM_SMEM>>>(
        p_bh, p_bl, p_wh, p_wl, b_fc2, p_x1,
        out, nullptr, nullptr, nullptr, M, C_EMB, C_HID);
}

// round 7
// speedup vs baseline: 7.4756x; 1.9616x over previous
#include <cuda_runtime.h>
#include <cuda_fp16.h>
#include <math.h>
#include <stdint.h>

// ---------------------------------------------------------------------------
// Problem constants
// ---------------------------------------------------------------------------
#define BATCH   64
#define SEQ     577
#define MTOK    (BATCH * SEQ)      // 36928
#define MPAD    36992              // 289 * 128
#define C_EMB   768
#define C_QKV   2304
#define C_HID   3072
#define NHEAD   12
#define HDIM    64

#define EPI_BIAS_RES  1
#define EPI_GELU_H    2
#define EPI_HALF      3

// ---------------------------------------------------------------------------
// Scratch (device globals)
// ---------------------------------------------------------------------------
__device__ __half g_qkvh[(size_t)MTOK * C_QKV];       // qkv proj, fp16 row-major
__device__ float  g_x1 [(size_t)MTOK * C_EMB];        // residual 1
// fp16 activations, chunked+swizzled: [K/64][MPAD rows][64 fp16 = 128B]
__device__ __half g_actA[(size_t)MPAD * C_EMB];       // K=768 activations
__device__ __half g_actB[(size_t)MPAD * C_HID];       // ff activations (K=3072)
// fp16 weights, transposed chunked+swizzled: [K/64][N][64 fp16]
__device__ __half g_w   [(size_t)C_HID * C_EMB];

// ---------------------------------------------------------------------------
// PTX helpers (sm_80/90-baseline: cp.async, bulk-async, mbarrier, ldmatrix, mma)
// ---------------------------------------------------------------------------
__device__ __forceinline__ uint32_t cvta_s(const void* p) {
    uint32_t a;
    asm("{ .reg .u64 t; cvta.to.shared.u64 t, %1; cvt.u32.u64 %0, t; }"
        : "=r"(a) : "l"(p));
    return a;
}
__device__ __forceinline__ void mbar_init(uint32_t mbar, uint32_t cnt) {
    asm volatile("mbarrier.init.shared.b64 [%0], %1;" :: "r"(mbar), "r"(cnt) : "memory");
}
__device__ __forceinline__ void mbar_expect_tx(uint32_t mbar, uint32_t bytes) {
    asm volatile("mbarrier.arrive.expect_tx.shared.b64 _, [%0], %1;"
                 :: "r"(mbar), "r"(bytes) : "memory");
}
__device__ __forceinline__ void mbar_arrive(uint32_t mbar) {
    asm volatile("mbarrier.arrive.shared.b64 _, [%0];" :: "r"(mbar) : "memory");
}
__device__ __forceinline__ void mbar_wait(uint32_t mbar, uint32_t phase) {
    asm volatile(
        "{\n\t"
        ".reg .pred P1;\n\t"
        "WAIT_LOOP_%=:\n\t"
        "mbarrier.try_wait.parity.acquire.cta.shared::cta.b64 P1, [%0], %1, 0x989680;\n\t"
        "@P1 bra.uni WAIT_DONE_%=;\n\t"
        "bra.uni WAIT_LOOP_%=;\n\t"
        "WAIT_DONE_%=:\n\t"
        "}"
        :: "r"(mbar), "r"(phase) : "memory");
}
__device__ __forceinline__ void bulk_ldg(uint32_t dst, const void* src,
                                         uint32_t bytes, uint32_t mbar) {
    asm volatile(
        "cp.async.bulk.shared::cluster.global.mbarrier::complete_tx::bytes "
        "[%0], [%1], %2, [%3];"
        :: "r"(dst), "l"(src), "r"(bytes), "r"(mbar) : "memory");
}
__device__ __forceinline__ void cp16(uint32_t dst, const void* src, uint32_t srcsize) {
    asm volatile("cp.async.cg.shared.global [%0], [%1], 16, %2;"
                 :: "r"(dst), "l"(src), "r"(srcsize) : "memory");
}
__device__ __forceinline__ void cp_commit() {
    asm volatile("cp.async.commit_group;" ::: "memory");
}
__device__ __forceinline__ void cp_wait0() {
    asm volatile("cp.async.wait_group 0;" ::: "memory");
}
__device__ __forceinline__ void ldsm4(uint32_t* r, uint32_t addr) {
    asm volatile("ldmatrix.sync.aligned.m8n8.x4.shared.b16 {%0,%1,%2,%3}, [%4];"
                 : "=r"(r[0]), "=r"(r[1]), "=r"(r[2]), "=r"(r[3]) : "r"(addr));
}
__device__ __forceinline__ void ldsm4t(uint32_t* r, uint32_t addr) {
    asm volatile("ldmatrix.sync.aligned.m8n8.x4.trans.shared.b16 {%0,%1,%2,%3}, [%4];"
                 : "=r"(r[0]), "=r"(r[1]), "=r"(r[2]), "=r"(r[3]) : "r"(addr));
}
__device__ __forceinline__ void mma_f16(float* c, const uint32_t* a, const uint32_t* b) {
    asm volatile(
        "mma.sync.aligned.m16n8k16.row.col.f32.f16.f16.f32 "
        "{%0,%1,%2,%3},{%4,%5,%6,%7},{%8,%9},{%0,%1,%2,%3};"
        : "+f"(c[0]), "+f"(c[1]), "+f"(c[2]), "+f"(c[3])
        : "r"(a[0]), "r"(a[1]), "r"(a[2]), "r"(a[3]), "r"(b[0]), "r"(b[1]));
}

// ---------------------------------------------------------------------------
// Fused LayerNorm + fp16 convert (K=768) -> chunked swizzled activations
// ---------------------------------------------------------------------------
__global__ __launch_bounds__(256) void ln_f16_ker(const float* __restrict__ x,
                                                  const float* __restrict__ gamma,
                                                  const float* __restrict__ beta,
                                                  uint8_t* __restrict__ dst)
{
    const int row = blockIdx.x;
    const float* xr = x + (size_t)row * C_EMB;
    float s = 0.f, s2 = 0.f;
    #pragma unroll
    for (int c = threadIdx.x; c < C_EMB; c += 256) {
        float v = xr[c];
        s += v; s2 += v * v;
    }
    #pragma unroll
    for (int off = 16; off > 0; off >>= 1) {
        s  += __shfl_down_sync(0xFFFFFFFFu, s,  off);
        s2 += __shfl_down_sync(0xFFFFFFFFu, s2, off);
    }
    __shared__ float shs[8], shs2[8];
    const int lane = threadIdx.x & 31, warp = threadIdx.x >> 5;
    if (lane == 0) { shs[warp] = s; shs2[warp] = s2; }
    __syncthreads();
    if (threadIdx.x == 0) {
        float ts = 0.f, ts2 = 0.f;
        #pragma unroll
        for (int w = 0; w < 8; w++) { ts += shs[w]; ts2 += shs2[w]; }
        float mean = ts * (1.0f / C_EMB);
        float var  = ts2 * (1.0f / C_EMB) - mean * mean;
        shs[0]  = mean;
        shs2[0] = rsqrtf(var + 1e-5f);
    }
    __syncthreads();
    const float mean = shs[0], rstd = shs2[0];
    if (threadIdx.x < 96) {
        const int k = threadIdx.x * 8;
        union { __half h[8]; uint4 u; } uo;
        #pragma unroll
        for (int i = 0; i < 8; i++) {
            float v = (xr[k + i] - mean) * rstd * gamma[k + i] + beta[k + i];
            uo.h[i] = __float2half_rn(v);
        }
        size_t base = ((size_t)(k >> 6) * MPAD + row) * 128
                    + ((uint32_t)((k & 63) * 2) ^ (uint32_t)((row & 7) << 4));
        *(uint4*)(dst + base) = uo.u;
    }
}

// ---------------------------------------------------------------------------
// convT: fp32 weights [K,N] -> transposed fp16 chunked swizzled [K/64][N][64]
// ---------------------------------------------------------------------------
__global__ void convT_ker(const float* __restrict__ w,
                          uint8_t* __restrict__ dst, int K, int N)
{
    __shared__ float tile[32][33];
    const int n0 = blockIdx.x * 32, k0 = blockIdx.y * 32;
    const int tx = threadIdx.x, ty = threadIdx.y;
    for (int i = ty; i < 32; i += 4)
        tile[i][tx] = w[(size_t)(k0 + i) * N + n0 + tx];
    __syncthreads();
    const int n = n0 + tx;
    const int k = k0 + ty * 8;
    union { __half h[8]; uint4 u; } uo;
    #pragma unroll
    for (int i = 0; i < 8; i++)
        uo.h[i] = __float2half_rn(tile[ty * 8 + i][tx]);
    size_t base = ((size_t)(k >> 6) * N + n) * 128
                + ((uint32_t)((k & 63) * 2) ^ (uint32_t)((n & 7) << 4));
    *(uint4*)(dst + base) = uo.u;
}

// ---------------------------------------------------------------------------
// Single-pass fp16 warp-MMA GEMM, 3-stage cp.async.bulk pipeline, 2 CTAs/SM.
// BM=128, BN=128, BK=64, 256 thr (8 warps 4x2, warp tile 32x64).
// ---------------------------------------------------------------------------
#define NSTAGE      3
#define STAGE_BYTES 32768     // A 16K | B 16K
#define GEMM_SMEM   (NSTAGE * STAGE_BYTES + 1024)

template<int EPI>
__global__ __launch_bounds__(256, 2) void gemm_f16_ker(
    const uint8_t* __restrict__ A, const uint8_t* __restrict__ B,
    const float* __restrict__ bias, const float* __restrict__ res,
    float* __restrict__ C, __half* __restrict__ Ch, uint8_t* __restrict__ Sx,
    int M, int N, int K)
{
    extern __shared__ uint8_t dynsmem[];
    __shared__ __align__(8) uint64_t s_bar[2 * NSTAGE];

    const int t = threadIdx.x, lane = t & 31, wid = t >> 5;
    const int wm = wid >> 1, wn = wid & 1;
    const int bm = blockIdx.y * 128, bn = blockIdx.x * 128;

    const uint32_t sbase = (cvta_s(dynsmem) + 1023u) & ~1023u;
    uint32_t bfull[NSTAGE], bempty[NSTAGE];
    #pragma unroll
    for (int s = 0; s < NSTAGE; s++) {
        bfull[s]  = cvta_s(&s_bar[s]);
        bempty[s] = cvta_s(&s_bar[NSTAGE + s]);
    }
    if (t == 0) {
        #pragma unroll
        for (int s = 0; s < NSTAGE; s++) {
            mbar_init(bfull[s], 1);
            mbar_init(bempty[s], 8);
        }
    }
    __syncthreads();

    const int nc = K >> 6;
    auto issue = [&](int c) {
        const int s = c % NSTAGE;
        const uint32_t sb = sbase + (uint32_t)s * STAGE_BYTES;
        mbar_expect_tx(bfull[s], STAGE_BYTES);
        bulk_ldg(sb,         A + ((size_t)c * MPAD + bm) * 128, 16384, bfull[s]);
        bulk_ldg(sb + 16384, B + ((size_t)c * N + bn) * 128,    16384, bfull[s]);
    };
    if (t == 0) {
        const int pre = nc < NSTAGE ? nc : NSTAGE;
        for (int c = 0; c < pre; c++) issue(c);
    }

    const uint32_t sw = (uint32_t)(lane & 7) << 4;
    uint32_t rta[2], rtb[4];
    {
        const int rowoff = ((lane >> 3) & 1) * 8 + (lane & 7);
        rta[0] = (uint32_t)(wm * 32 +  0 + rowoff) * 128;
        rta[1] = (uint32_t)(wm * 32 + 16 + rowoff) * 128;
        const int nt = lane >> 4;
        #pragma unroll
        for (int j = 0; j < 4; j++)
            rtb[j] = (uint32_t)(wn * 64 + (2 * j + nt) * 8 + (lane & 7)) * 128 + 16384;
    }
    const uint32_t khA16 = (uint32_t)(lane >> 4) * 16;
    const uint32_t khB16 = (uint32_t)((lane >> 3) & 1) * 16;

    float acc[2][8][4];
    #pragma unroll
    for (int mi = 0; mi < 2; mi++)
        #pragma unroll
        for (int ni = 0; ni < 8; ni++)
            #pragma unroll
            for (int r = 0; r < 4; r++) acc[mi][ni][r] = 0.f;

    int fph[NSTAGE], eph[NSTAGE];
    #pragma unroll
    for (int s = 0; s < NSTAGE; s++) { fph[s] = 0; eph[s] = 0; }

    for (int c = 0; c < nc; c++) {
        const int s = c % NSTAGE;
        mbar_wait(bfull[s], fph[s]); fph[s] ^= 1;
        const uint32_t sb = sbase + (uint32_t)s * STAGE_BYTES;
        #pragma unroll
        for (int ks = 0; ks < 4; ks++) {
            const uint32_t offA = (uint32_t)(ks * 32 + khA16) ^ sw;
            const uint32_t offB = (uint32_t)(ks * 32 + khB16) ^ sw;
            uint32_t a[2][4], b[4][4];
            ldsm4(a[0], sb + rta[0] + offA);
            ldsm4(a[1], sb + rta[1] + offA);
            #pragma unroll
            for (int j = 0; j < 4; j++)
                ldsm4(b[j], sb + rtb[j] + offB);
            #pragma unroll
            for (int mi = 0; mi < 2; mi++)
                #pragma unroll
                for (int j = 0; j < 4; j++) {
                    mma_f16(acc[mi][2 * j],     a[mi], &b[j][0]);
                    mma_f16(acc[mi][2 * j + 1], a[mi], &b[j][2]);
                }
        }
        if (lane == 0) mbar_arrive(bempty[s]);
        if (t == 0 && c + NSTAGE < nc) {
            mbar_wait(bempty[s], eph[s]); eph[s] ^= 1;
            issue(c + NSTAGE);
        }
    }

    // epilogue
    const int row0 = bm + wm * 32 + (lane >> 2);
    const int col0 = bn + wn * 64 + (lane & 3) * 2;
    #pragma unroll
    for (int mi = 0; mi < 2; mi++) {
        #pragma unroll
        for (int ni = 0; ni < 8; ni++) {
            const int col = col0 + ni * 8;
            float bb0 = 0.f, bb1 = 0.f;
            if (EPI != EPI_HALF) { bb0 = bias[col]; bb1 = bias[col + 1]; }
            #pragma unroll
            for (int half = 0; half < 2; half++) {
                const int row = row0 + mi * 16 + half * 8;
                if (row < M) {
                    float v0 = acc[mi][ni][half * 2]     + bb0;
                    float v1 = acc[mi][ni][half * 2 + 1] + bb1;
                    if (EPI == EPI_HALF) {
                        __half2 h2 = __floats2half2_rn(acc[mi][ni][half * 2],
                                                       acc[mi][ni][half * 2 + 1]);
                        *(uint32_t*)(Ch + (size_t)row * N + col) = *(uint32_t*)&h2;
                    } else if (EPI == EPI_GELU_H) {
                        v0 = 0.5f * v0 * (1.0f + erff(v0 * 0.70710678118654752f));
                        v1 = 0.5f * v1 * (1.0f + erff(v1 * 0.70710678118654752f));
                        __half2 h2 = __floats2half2_rn(v0, v1);
                        size_t base = ((size_t)(col >> 6) * MPAD + row) * 128
                                    + ((uint32_t)(2 * (col & 63)) ^ (uint32_t)((row & 7) << 4));
                        *(uint32_t*)(Sx + base) = *(uint32_t*)&h2;
                    } else { // EPI_BIAS_RES
                        const float2 r2 = *(const float2*)(res + (size_t)row * N + col);
                        *(float2*)(C + (size_t)row * N + col) =
                            make_float2(v0 + r2.x, v1 + r2.y);
                    }
                }
            }
        }
    }
}

// ---------------------------------------------------------------------------
// fp16 tensor-core flash attention with cp.async double-buffered K/V.
// grid (10, B*H), 128 threads (4 warps). Epilogue writes fp16 chunked acts.
// ---------------------------------------------------------------------------
#define NITER ((SEQ + 63) / 64)    // 10

__global__ __launch_bounds__(128) void attn_ker(const __half* __restrict__ qkv,
                                                uint8_t* __restrict__ oa)
{
    const int bh = blockIdx.y;
    const int b  = bh / NHEAD;
    const int h  = bh % NHEAD;
    const int q0 = blockIdx.x * 64;
    const int t  = threadIdx.x, lane = t & 31, w = t >> 5;

    __shared__ __align__(16) uint8_t qs[64 * 128];
    __shared__ __align__(16) uint8_t ks[2][64 * 128];
    __shared__ __align__(16) uint8_t vs[2][64 * 128];
    const uint32_t qsa = cvta_s(qs);
    const uint32_t ksa[2] = { cvta_s(ks[0]), cvta_s(ks[1]) };
    const uint32_t vsa[2] = { cvta_s(vs[0]), cvta_s(vs[1]) };

    // issue K/V tile j0 into buffer bi (cp.async, zero-fill OOB rows)
    auto issue_kv = [&](int j0, int bi) {
        for (int idx = t; idx < 512; idx += 128) {
            const int r = idx >> 3, g = idx & 7;
            const int kr = j0 + r;
            const int krc = kr < SEQ ? kr : SEQ - 1;
            const uint32_t sz = kr < SEQ ? 16u : 0u;
            const __half* src = qkv + (size_t)(b * SEQ + krc) * C_QKV + h * HDIM + g * 8;
            const uint32_t off = r * 128 + ((g * 16) ^ ((r & 7) << 4));
            cp16(ksa[bi] + off, src + C_EMB,     sz);
            cp16(vsa[bi] + off, src + 2 * C_EMB, sz);
        }
        cp_commit();
    };

    issue_kv(0, 0);

    // load Q tile (plain loads)
    for (int idx = t; idx < 1024; idx += 128) {
        const int r = idx >> 4, g = idx & 15;
        const int qr = q0 + r;
        uint2 val = make_uint2(0u, 0u);
        if (qr < SEQ)
            val = *(const uint2*)(qkv + (size_t)(b * SEQ + qr) * C_QKV + h * HDIM + g * 4);
        *(uint2*)(qs + r * 128 + ((g * 8) ^ ((r & 7) << 4))) = val;
    }
    __syncthreads();

    const uint32_t swl = (uint32_t)(lane & 7) << 4;
    const uint32_t nt  = (uint32_t)(lane >> 4);
    const uint32_t rhalf = (uint32_t)((lane >> 3) & 1);
    const uint32_t khA = nt * 16;
    const uint32_t khB = rhalf * 16;

    // Q A-fragments (loop invariant)
    uint32_t qa[4][4];
    {
        const uint32_t rowA = (uint32_t)(w * 16 + rhalf * 8 + (lane & 7)) * 128;
        #pragma unroll
        for (int kc = 0; kc < 4; kc++)
            ldsm4(qa[kc], qsa + rowA + (((uint32_t)(kc * 32) + khA) ^ swl));
    }

    float m0 = -1e30f, m1 = -1e30f, l0 = 0.f, l1 = 0.f;
    float o[8][4];
    #pragma unroll
    for (int nj = 0; nj < 8; nj++)
        #pragma unroll
        for (int r = 0; r < 4; r++) o[nj][r] = 0.f;

    const int c0 = (lane & 3) * 2;

    for (int i = 0; i < NITER; i++) {
        const int bi = i & 1;
        const int j0 = i * 64;
        cp_wait0();            // own loads of tile i complete
        __syncthreads();       // tile i visible to all; all done computing i-1
        if (i + 1 < NITER) issue_kv(j0 + 64, bi ^ 1);   // overlaps compute below

        // S = Q K^T
        float s[8][4];
        #pragma unroll
        for (int nj = 0; nj < 8; nj++)
            #pragma unroll
            for (int r = 0; r < 4; r++) s[nj][r] = 0.f;
        #pragma unroll
        for (int kc = 0; kc < 4; kc++) {
            #pragma unroll
            for (int j = 0; j < 4; j++) {
                uint32_t bb[4];
                const uint32_t row = (uint32_t)((2 * j + nt) * 8 + (lane & 7)) * 128;
                ldsm4(bb, ksa[bi] + row + (((uint32_t)(kc * 32) + khB) ^ swl));
                mma_f16(s[2 * j],     qa[kc], &bb[0]);
                mma_f16(s[2 * j + 1], qa[kc], &bb[2]);
            }
        }

        // scale + mask
        #pragma unroll
        for (int nj = 0; nj < 8; nj++) {
            const int col = j0 + nj * 8 + c0;
            const bool ok0 = col < SEQ, ok1 = (col + 1) < SEQ;
            s[nj][0] = ok0 ? s[nj][0] * 0.125f : -1e30f;
            s[nj][1] = ok1 ? s[nj][1] * 0.125f : -1e30f;
            s[nj][2] = ok0 ? s[nj][2] * 0.125f : -1e30f;
            s[nj][3] = ok1 ? s[nj][3] * 0.125f : -1e30f;
        }

        // online softmax (rows r and r+8; quad-lane reduction)
        float mx0 = -1e30f, mx1 = -1e30f;
        #pragma unroll
        for (int nj = 0; nj < 8; nj++) {
            mx0 = fmaxf(mx0, fmaxf(s[nj][0], s[nj][1]));
            mx1 = fmaxf(mx1, fmaxf(s[nj][2], s[nj][3]));
        }
        mx0 = fmaxf(mx0, __shfl_xor_sync(0xFFFFFFFFu, mx0, 1));
        mx0 = fmaxf(mx0, __shfl_xor_sync(0xFFFFFFFFu, mx0, 2));
        mx1 = fmaxf(mx1, __shfl_xor_sync(0xFFFFFFFFu, mx1, 1));
        mx1 = fmaxf(mx1, __shfl_xor_sync(0xFFFFFFFFu, mx1, 2));
        const float nm0 = fmaxf(m0, mx0), nm1 = fmaxf(m1, mx1);
        const float cr0 = __expf(m0 - nm0), cr1 = __expf(m1 - nm1);
        m0 = nm0; m1 = nm1;
        float rs0 = 0.f, rs1 = 0.f;
        #pragma unroll
        for (int nj = 0; nj < 8; nj++) {
            float p0 = __expf(s[nj][0] - m0);
            float p1 = __expf(s[nj][1] - m0);
            float p2 = __expf(s[nj][2] - m1);
            float p3 = __expf(s[nj][3] - m1);
            s[nj][0] = p0; s[nj][1] = p1; s[nj][2] = p2; s[nj][3] = p3;
            rs0 += p0 + p1;
            rs1 += p2 + p3;
        }
        rs0 += __shfl_xor_sync(0xFFFFFFFFu, rs0, 1);
        rs0 += __shfl_xor_sync(0xFFFFFFFFu, rs0, 2);
        rs1 += __shfl_xor_sync(0xFFFFFFFFu, rs1, 1);
        rs1 += __shfl_xor_sync(0xFFFFFFFFu, rs1, 2);
        l0 = l0 * cr0 + rs0;
        l1 = l1 * cr1 + rs1;
        #pragma unroll
        for (int nj = 0; nj < 8; nj++) {
            o[nj][0] *= cr0; o[nj][1] *= cr0;
            o[nj][2] *= cr1; o[nj][3] *= cr1;
        }

        // O += P V
        #pragma unroll
        for (int kc = 0; kc < 4; kc++) {
            uint32_t pa[4];
            {
                __half2 t0 = __floats2half2_rn(s[2 * kc][0],     s[2 * kc][1]);
                __half2 t1 = __floats2half2_rn(s[2 * kc][2],     s[2 * kc][3]);
                __half2 t2 = __floats2half2_rn(s[2 * kc + 1][0], s[2 * kc + 1][1]);
                __half2 t3 = __floats2half2_rn(s[2 * kc + 1][2], s[2 * kc + 1][3]);
                pa[0] = *(uint32_t*)&t0; pa[1] = *(uint32_t*)&t1;
                pa[2] = *(uint32_t*)&t2; pa[3] = *(uint32_t*)&t3;
            }
            const uint32_t row = (uint32_t)(kc * 16 + rhalf * 8 + (lane & 7)) * 128;
            #pragma unroll
            for (int j = 0; j < 4; j++) {
                uint32_t vb[4];
                const uint32_t colb = 16u * (uint32_t)(2 * j + nt);
                ldsm4t(vb, vsa[bi] + row + (colb ^ swl));
                mma_f16(o[2 * j],     pa, &vb[0]);
                mma_f16(o[2 * j + 1], pa, &vb[2]);
            }
        }
    }

    // epilogue: normalize + fp16 into chunked activation buffer (chunk = head)
    #pragma unroll
    for (int half = 0; half < 2; half++) {
        const int qr = q0 + w * 16 + (lane >> 2) + half * 8;
        if (qr < SEQ) {
            const float inv = 1.0f / (half ? l1 : l0);
            const size_t mtok = (size_t)b * SEQ + qr;
            const uint32_t swr = ((uint32_t)(mtok & 7)) << 4;
            const size_t rowbase = ((size_t)h * MPAD + mtok) * 128;
            #pragma unroll
            for (int nj = 0; nj < 8; nj++) {
                const int d = nj * 8 + c0;
                __half2 h2 = __floats2half2_rn(o[nj][half * 2] * inv,
                                               o[nj][half * 2 + 1] * inv);
                *(uint32_t*)(oa + rowbase + (((uint32_t)(2 * d)) ^ swr)) = *(uint32_t*)&h2;
            }
        }
    }
}

// ---------------------------------------------------------------------------
// Launch
// ---------------------------------------------------------------------------
extern "C" void kernel_launch(void* const* d_in, const int* in_sizes, int n_in,
                              void* d_out, int out_size)
{
    const float* x      = (const float*)d_in[0];
    const float* ln1_g  = (const float*)d_in[1];
    const float* ln1_b  = (const float*)d_in[2];
    const float* w_qkv  = (const float*)d_in[3];
    const float* w_proj = (const float*)d_in[4];
    const float* b_proj = (const float*)d_in[5];
    const float* ln2_g  = (const float*)d_in[6];
    const float* ln2_b  = (const float*)d_in[7];
    const float* w_fc1  = (const float*)d_in[8];
    const float* b_fc1  = (const float*)d_in[9];
    const float* w_fc2  = (const float*)d_in[10];
    const float* b_fc2  = (const float*)d_in[11];
    float* out = (float*)d_out;

    __half *p_qkvh, *p_w; float* p_x1;
    uint8_t *p_actA, *p_actB;
    cudaGetSymbolAddress((void**)&p_qkvh, g_qkvh);
    cudaGetSymbolAddress((void**)&p_x1,   g_x1);
    cudaGetSymbolAddress((void**)&p_actA, g_actA);
    cudaGetSymbolAddress((void**)&p_actB, g_actB);
    cudaGetSymbolAddress((void**)&p_w,    g_w);
    uint8_t* p_wb = (uint8_t*)p_w;

    cudaFuncSetAttribute(gemm_f16_ker<EPI_BIAS_RES>,
                         cudaFuncAttributeMaxDynamicSharedMemorySize, GEMM_SMEM);
    cudaFuncSetAttribute(gemm_f16_ker<EPI_GELU_H>,
                         cudaFuncAttributeMaxDynamicSharedMemorySize, GEMM_SMEM);
    cudaFuncSetAttribute(gemm_f16_ker<EPI_HALF>,
                         cudaFuncAttributeMaxDynamicSharedMemorySize, GEMM_SMEM);

    const int M = MTOK;
    const int MY = (M + 127) / 128;   // 289
    const dim3 blkT(32, 4);

    // 1) LN1 -> fp16 acts A
    ln_f16_ker<<<M, 256>>>(x, ln1_g, ln1_b, p_actA);
    // 2) convert w_qkv
    convT_ker<<<dim3(C_QKV / 32, C_EMB / 32), blkT>>>(w_qkv, p_wb, C_EMB, C_QKV);
    // 3) qkv = h @ w_qkv -> fp16 row-major
    gemm_f16_ker<EPI_HALF><<<dim3(C_QKV / 128, MY), 256, GEMM_SMEM>>>(
        p_actA, p_wb, nullptr, nullptr, nullptr, p_qkvh, nullptr, M, C_QKV, C_EMB);
    // 4) flash attention -> fp16 acts A
    attn_ker<<<dim3(NITER, BATCH * NHEAD), 128>>>(p_qkvh, p_actA);
    // 5) convert w_proj
    convT_ker<<<dim3(C_EMB / 32, C_EMB / 32), blkT>>>(w_proj, p_wb, C_EMB, C_EMB);
    // 6) x1 = x + att @ w_proj + b_proj
    gemm_f16_ker<EPI_BIAS_RES><<<dim3(C_EMB / 128, MY), 256, GEMM_SMEM>>>(
        p_actA, p_wb, b_proj, x, p_x1, nullptr, nullptr, M, C_EMB, C_EMB);
    // 7) LN2 -> fp16 acts A
    ln_f16_ker<<<M, 256>>>(p_x1, ln2_g, ln2_b, p_actA);
    // 8) convert w_fc1
    convT_ker<<<dim3(C_HID / 32, C_EMB / 32), blkT>>>(w_fc1, p_wb, C_EMB, C_HID);
    // 9) ff = gelu(h @ w_fc1 + b_fc1) -> fp16 acts B
    gemm_f16_ker<EPI_GELU_H><<<dim3(C_HID / 128, MY), 256, GEMM_SMEM>>>(
        p_actA, p_wb, b_fc1, nullptr, nullptr, nullptr, p_actB, M, C_HID, C_EMB);
    // 10) convert w_fc2
    convT_ker<<<dim3(C_EMB / 32, C_HID / 32), blkT>>>(w_fc2, p_wb, C_HID, C_EMB);
    // 11) out = x1 + ff @ w_fc2 + b_fc2
    gemm_f16_ker<EPI_BIAS_RES><<<dim3(C_EMB / 128, MY), 256, GEMM_SMEM>>>(
        p_actB, p_wb, b_fc2, p_x1, out, nullptr, nullptr, M, C_EMB, C_HID);
}

// round 8
// speedup vs baseline: 7.6178x; 1.0190x over previous
#include <cuda_runtime.h>
#include <cuda_fp16.h>
#include <math.h>
#include <stdint.h>

// ---------------------------------------------------------------------------
// Problem constants
// ---------------------------------------------------------------------------
#define BATCH   64
#define SEQ     577
#define MTOK    (BATCH * SEQ)      // 36928
#define MPAD    36992              // 289 * 128
#define C_EMB   768
#define C_QKV   2304
#define C_HID   3072
#define NHEAD   12
#define HDIM    64

#define EPI_BIAS_RES  1
#define EPI_GELU_H    2
#define EPI_HALF      3

// ---------------------------------------------------------------------------
// Scratch (device globals)
// ---------------------------------------------------------------------------
__device__ __half g_qkvh[(size_t)MTOK * C_QKV];       // qkv proj, fp16 row-major
__device__ float  g_x1 [(size_t)MTOK * C_EMB];        // residual 1
// fp16 activations, chunked+swizzled: [K/64][MPAD rows][64 fp16 = 128B]
__device__ __half g_actA[(size_t)MPAD * C_EMB];
__device__ __half g_actB[(size_t)MPAD * C_HID];
// fp16 weights, transposed chunked+swizzled: [K/64][N][64 fp16]
__device__ __half g_w   [(size_t)C_HID * C_EMB];

// ---------------------------------------------------------------------------
// PTX helpers
// ---------------------------------------------------------------------------
__device__ __forceinline__ uint32_t cvta_s(const void* p) {
    uint32_t a;
    asm("{ .reg .u64 t; cvta.to.shared.u64 t, %1; cvt.u32.u64 %0, t; }"
        : "=r"(a) : "l"(p));
    return a;
}
__device__ __forceinline__ void mbar_init(uint32_t mbar, uint32_t cnt) {
    asm volatile("mbarrier.init.shared.b64 [%0], %1;" :: "r"(mbar), "r"(cnt) : "memory");
}
__device__ __forceinline__ void mbar_expect_tx(uint32_t mbar, uint32_t bytes) {
    asm volatile("mbarrier.arrive.expect_tx.shared.b64 _, [%0], %1;"
                 :: "r"(mbar), "r"(bytes) : "memory");
}
__device__ __forceinline__ void mbar_arrive(uint32_t mbar) {
    asm volatile("mbarrier.arrive.shared.b64 _, [%0];" :: "r"(mbar) : "memory");
}
__device__ __forceinline__ void mbar_wait(uint32_t mbar, uint32_t phase) {
    asm volatile(
        "{\n\t"
        ".reg .pred P1;\n\t"
        "WAIT_LOOP_%=:\n\t"
        "mbarrier.try_wait.parity.acquire.cta.shared::cta.b64 P1, [%0], %1, 0x989680;\n\t"
        "@P1 bra.uni WAIT_DONE_%=;\n\t"
        "bra.uni WAIT_LOOP_%=;\n\t"
        "WAIT_DONE_%=:\n\t"
        "}"
        :: "r"(mbar), "r"(phase) : "memory");
}
__device__ __forceinline__ void bulk_ldg(uint32_t dst, const void* src,
                                         uint32_t bytes, uint32_t mbar) {
    asm volatile(
        "cp.async.bulk.shared::cluster.global.mbarrier::complete_tx::bytes "
        "[%0], [%1], %2, [%3];"
        :: "r"(dst), "l"(src), "r"(bytes), "r"(mbar) : "memory");
}
__device__ __forceinline__ void cp16(uint32_t dst, const void* src, uint32_t srcsize) {
    asm volatile("cp.async.cg.shared.global [%0], [%1], 16, %2;"
                 :: "r"(dst), "l"(src), "r"(srcsize) : "memory");
}
__device__ __forceinline__ void cp_commit() {
    asm volatile("cp.async.commit_group;" ::: "memory");
}
__device__ __forceinline__ void cp_wait0() {
    asm volatile("cp.async.wait_group 0;" ::: "memory");
}
__device__ __forceinline__ void ldsm4(uint32_t* r, uint32_t addr) {
    asm volatile("ldmatrix.sync.aligned.m8n8.x4.shared.b16 {%0,%1,%2,%3}, [%4];"
                 : "=r"(r[0]), "=r"(r[1]), "=r"(r[2]), "=r"(r[3]) : "r"(addr));
}
__device__ __forceinline__ void ldsm4t(uint32_t* r, uint32_t addr) {
    asm volatile("ldmatrix.sync.aligned.m8n8.x4.trans.shared.b16 {%0,%1,%2,%3}, [%4];"
                 : "=r"(r[0]), "=r"(r[1]), "=r"(r[2]), "=r"(r[3]) : "r"(addr));
}
__device__ __forceinline__ void mma_f16(float* c, const uint32_t* a, const uint32_t* b) {
    asm volatile(
        "mma.sync.aligned.m16n8k16.row.col.f32.f16.f16.f32 "
        "{%0,%1,%2,%3},{%4,%5,%6,%7},{%8,%9},{%0,%1,%2,%3};"
        : "+f"(c[0]), "+f"(c[1]), "+f"(c[2]), "+f"(c[3])
        : "r"(a[0]), "r"(a[1]), "r"(a[2]), "r"(a[3]), "r"(b[0]), "r"(b[1]));
}

// ---------------------------------------------------------------------------
// Fused LayerNorm + fp16 convert (K=768) -> chunked swizzled activations
// ---------------------------------------------------------------------------
__global__ __launch_bounds__(256) void ln_f16_ker(const float* __restrict__ x,
                                                  const float* __restrict__ gamma,
                                                  const float* __restrict__ beta,
                                                  uint8_t* __restrict__ dst)
{
    const int row = blockIdx.x;
    const float* xr = x + (size_t)row * C_EMB;
    float s = 0.f, s2 = 0.f;
    #pragma unroll
    for (int c = threadIdx.x; c < C_EMB; c += 256) {
        float v = xr[c];
        s += v; s2 += v * v;
    }
    #pragma unroll
    for (int off = 16; off > 0; off >>= 1) {
        s  += __shfl_down_sync(0xFFFFFFFFu, s,  off);
        s2 += __shfl_down_sync(0xFFFFFFFFu, s2, off);
    }
    __shared__ float shs[8], shs2[8];
    const int lane = threadIdx.x & 31, warp = threadIdx.x >> 5;
    if (lane == 0) { shs[warp] = s; shs2[warp] = s2; }
    __syncthreads();
    if (threadIdx.x == 0) {
        float ts = 0.f, ts2 = 0.f;
        #pragma unroll
        for (int w = 0; w < 8; w++) { ts += shs[w]; ts2 += shs2[w]; }
        float mean = ts * (1.0f / C_EMB);
        float var  = ts2 * (1.0f / C_EMB) - mean * mean;
        shs[0]  = mean;
        shs2[0] = rsqrtf(var + 1e-5f);
    }
    __syncthreads();
    const float mean = shs[0], rstd = shs2[0];
    if (threadIdx.x < 96) {
        const int k = threadIdx.x * 8;
        union { __half h[8]; uint4 u; } uo;
        #pragma unroll
        for (int i = 0; i < 8; i++) {
            float v = (xr[k + i] - mean) * rstd * gamma[k + i] + beta[k + i];
            uo.h[i] = __float2half_rn(v);
        }
        size_t base = ((size_t)(k >> 6) * MPAD + row) * 128
                    + ((uint32_t)((k & 63) * 2) ^ (uint32_t)((row & 7) << 4));
        *(uint4*)(dst + base) = uo.u;
    }
}

// ---------------------------------------------------------------------------
// convT: fp32 weights [K,N] -> transposed fp16 chunked swizzled [K/64][N][64]
// ---------------------------------------------------------------------------
__global__ void convT_ker(const float* __restrict__ w,
                          uint8_t* __restrict__ dst, int K, int N)
{
    __shared__ float tile[32][33];
    const int n0 = blockIdx.x * 32, k0 = blockIdx.y * 32;
    const int tx = threadIdx.x, ty = threadIdx.y;
    for (int i = ty; i < 32; i += 4)
        tile[i][tx] = w[(size_t)(k0 + i) * N + n0 + tx];
    __syncthreads();
    const int n = n0 + tx;
    const int k = k0 + ty * 8;
    union { __half h[8]; uint4 u; } uo;
    #pragma unroll
    for (int i = 0; i < 8; i++)
        uo.h[i] = __float2half_rn(tile[ty * 8 + i][tx]);
    size_t base = ((size_t)(k >> 6) * N + n) * 128
                + ((uint32_t)((k & 63) * 2) ^ (uint32_t)((n & 7) << 4));
    *(uint4*)(dst + base) = uo.u;
}

// ---------------------------------------------------------------------------
// Single-pass fp16 warp-MMA GEMM: BM=128, BN=256, BK=64, 3-stage bulk pipeline.
// 256 thr, 8 warps (4x2), warp tile 32x128.
// ---------------------------------------------------------------------------
#define NSTAGE      3
#define STAGE_BYTES 49152     // A 16K | B 32K
#define GEMM_SMEM   (NSTAGE * STAGE_BYTES + 1024)

template<int EPI>
__global__ __launch_bounds__(256, 1) void gemm_f16_ker(
    const uint8_t* __restrict__ A, const uint8_t* __restrict__ B,
    const float* __restrict__ bias, const float* __restrict__ res,
    float* __restrict__ C, __half* __restrict__ Ch, uint8_t* __restrict__ Sx,
    int M, int N, int K)
{
    extern __shared__ uint8_t dynsmem[];
    __shared__ __align__(8) uint64_t s_bar[2 * NSTAGE];

    const int t = threadIdx.x, lane = t & 31, wid = t >> 5;
    const int wm = wid >> 1, wn = wid & 1;
    const int bm = blockIdx.y * 128, bn = blockIdx.x * 256;

    const uint32_t sbase = (cvta_s(dynsmem) + 1023u) & ~1023u;
    uint32_t bfull[NSTAGE], bempty[NSTAGE];
    #pragma unroll
    for (int s = 0; s < NSTAGE; s++) {
        bfull[s]  = cvta_s(&s_bar[s]);
        bempty[s] = cvta_s(&s_bar[NSTAGE + s]);
    }
    if (t == 0) {
        #pragma unroll
        for (int s = 0; s < NSTAGE; s++) {
            mbar_init(bfull[s], 1);
            mbar_init(bempty[s], 8);
        }
    }
    __syncthreads();

    const int nc = K >> 6;
    auto issue = [&](int c) {
        const int s = c % NSTAGE;
        const uint32_t sb = sbase + (uint32_t)s * STAGE_BYTES;
        mbar_expect_tx(bfull[s], STAGE_BYTES);
        bulk_ldg(sb,         A + ((size_t)c * MPAD + bm) * 128, 16384, bfull[s]);
        bulk_ldg(sb + 16384, B + ((size_t)c * N + bn) * 128,    32768, bfull[s]);
    };
    if (t == 0) {
        const int pre = nc < NSTAGE ? nc : NSTAGE;
        for (int c = 0; c < pre; c++) issue(c);
    }

    const uint32_t sw = (uint32_t)(lane & 7) << 4;
    uint32_t rta[2], rtb[8];
    {
        const int rowoff = ((lane >> 3) & 1) * 8 + (lane & 7);
        rta[0] = (uint32_t)(wm * 32 +  0 + rowoff) * 128;
        rta[1] = (uint32_t)(wm * 32 + 16 + rowoff) * 128;
        const int nt = lane >> 4;
        #pragma unroll
        for (int j = 0; j < 8; j++)
            rtb[j] = (uint32_t)(wn * 128 + (2 * j + nt) * 8 + (lane & 7)) * 128 + 16384;
    }
    const uint32_t khA16 = (uint32_t)(lane >> 4) * 16;
    const uint32_t khB16 = (uint32_t)((lane >> 3) & 1) * 16;

    float acc[2][16][4];
    #pragma unroll
    for (int mi = 0; mi < 2; mi++)
        #pragma unroll
        for (int ni = 0; ni < 16; ni++)
            #pragma unroll
            for (int r = 0; r < 4; r++) acc[mi][ni][r] = 0.f;

    int fph[NSTAGE], eph[NSTAGE];
    #pragma unroll
    for (int s = 0; s < NSTAGE; s++) { fph[s] = 0; eph[s] = 0; }

    for (int c = 0; c < nc; c++) {
        const int s = c % NSTAGE;
        mbar_wait(bfull[s], fph[s]); fph[s] ^= 1;
        const uint32_t sb = sbase + (uint32_t)s * STAGE_BYTES;
        #pragma unroll
        for (int ks = 0; ks < 4; ks++) {
            const uint32_t offA = (uint32_t)(ks * 32 + khA16) ^ sw;
            const uint32_t offB = (uint32_t)(ks * 32 + khB16) ^ sw;
            uint32_t a[2][4];
            ldsm4(a[0], sb + rta[0] + offA);
            ldsm4(a[1], sb + rta[1] + offA);
            #pragma unroll
            for (int j = 0; j < 8; j++) {
                uint32_t b[4];
                ldsm4(b, sb + rtb[j] + offB);
                mma_f16(acc[0][2 * j],     a[0], &b[0]);
                mma_f16(acc[0][2 * j + 1], a[0], &b[2]);
                mma_f16(acc[1][2 * j],     a[1], &b[0]);
                mma_f16(acc[1][2 * j + 1], a[1], &b[2]);
            }
        }
        if (lane == 0) mbar_arrive(bempty[s]);
        if (t == 0 && c + NSTAGE < nc) {
            mbar_wait(bempty[s], eph[s]); eph[s] ^= 1;
            issue(c + NSTAGE);
        }
    }

    // epilogue
    const int row0 = bm + wm * 32 + (lane >> 2);
    const int col0 = bn + wn * 128 + (lane & 3) * 2;
    #pragma unroll
    for (int mi = 0; mi < 2; mi++) {
        #pragma unroll
        for (int ni = 0; ni < 16; ni++) {
            const int col = col0 + ni * 8;
            float bb0 = 0.f, bb1 = 0.f;
            if (EPI != EPI_HALF) { bb0 = bias[col]; bb1 = bias[col + 1]; }
            #pragma unroll
            for (int half = 0; half < 2; half++) {
                const int row = row0 + mi * 16 + half * 8;
                if (row < M) {
                    float v0 = acc[mi][ni][half * 2]     + bb0;
                    float v1 = acc[mi][ni][half * 2 + 1] + bb1;
                    if (EPI == EPI_HALF) {
                        __half2 h2 = __floats2half2_rn(acc[mi][ni][half * 2],
                                                       acc[mi][ni][half * 2 + 1]);
                        *(uint32_t*)(Ch + (size_t)row * N + col) = *(uint32_t*)&h2;
                    } else if (EPI == EPI_GELU_H) {
                        v0 = 0.5f * v0 * (1.0f + erff(v0 * 0.70710678118654752f));
                        v1 = 0.5f * v1 * (1.0f + erff(v1 * 0.70710678118654752f));
                        __half2 h2 = __floats2half2_rn(v0, v1);
                        size_t base = ((size_t)(col >> 6) * MPAD + row) * 128
                                    + ((uint32_t)(2 * (col & 63)) ^ (uint32_t)((row & 7) << 4));
                        *(uint32_t*)(Sx + base) = *(uint32_t*)&h2;
                    } else { // EPI_BIAS_RES
                        const float2 r2 = *(const float2*)(res + (size_t)row * N + col);
                        *(float2*)(C + (size_t)row * N + col) =
                            make_float2(v0 + r2.x, v1 + r2.y);
                    }
                }
            }
        }
    }
}

// ---------------------------------------------------------------------------
// fp16 flash attention; Q pre-scaled by 0.125 (exact), mask only on last iter.
// grid (10, B*H), 128 threads. cp.async double-buffered K/V.
// ---------------------------------------------------------------------------
#define NITER ((SEQ + 63) / 64)    // 10

__global__ __launch_bounds__(128) void attn_ker(const __half* __restrict__ qkv,
                                                uint8_t* __restrict__ oa)
{
    const int bh = blockIdx.y;
    const int b  = bh / NHEAD;
    const int h  = bh % NHEAD;
    const int q0 = blockIdx.x * 64;
    const int t  = threadIdx.x, lane = t & 31, w = t >> 5;

    __shared__ __align__(16) uint8_t qs[64 * 128];
    __shared__ __align__(16) uint8_t ks[2][64 * 128];
    __shared__ __align__(16) uint8_t vs[2][64 * 128];
    const uint32_t qsa = cvta_s(qs);
    const uint32_t ksa[2] = { cvta_s(ks[0]), cvta_s(ks[1]) };
    const uint32_t vsa[2] = { cvta_s(vs[0]), cvta_s(vs[1]) };

    auto issue_kv = [&](int j0, int bi) {
        for (int idx = t; idx < 512; idx += 128) {
            const int r = idx >> 3, g = idx & 7;
            const int kr = j0 + r;
            const int krc = kr < SEQ ? kr : SEQ - 1;
            const uint32_t sz = kr < SEQ ? 16u : 0u;
            const __half* src = qkv + (size_t)(b * SEQ + krc) * C_QKV + h * HDIM + g * 8;
            const uint32_t off = r * 128 + ((g * 16) ^ ((r & 7) << 4));
            cp16(ksa[bi] + off, src + C_EMB,     sz);
            cp16(vsa[bi] + off, src + 2 * C_EMB, sz);
        }
        cp_commit();
    };

    issue_kv(0, 0);

    // load Q tile, pre-scaled by 1/8 (exact power of two in fp16)
    const __half2 qsc = __floats2half2_rn(0.125f, 0.125f);
    for (int idx = t; idx < 1024; idx += 128) {
        const int r = idx >> 4, g = idx & 15;
        const int qr = q0 + r;
        uint2 val = make_uint2(0u, 0u);
        if (qr < SEQ) {
            val = *(const uint2*)(qkv + (size_t)(b * SEQ + qr) * C_QKV + h * HDIM + g * 4);
            __half2* hp = (__half2*)&val;
            hp[0] = __hmul2(hp[0], qsc);
            hp[1] = __hmul2(hp[1], qsc);
        }
        *(uint2*)(qs + r * 128 + ((g * 8) ^ ((r & 7) << 4))) = val;
    }
    __syncthreads();

    const uint32_t swl = (uint32_t)(lane & 7) << 4;
    const uint32_t nt  = (uint32_t)(lane >> 4);
    const uint32_t rhalf = (uint32_t)((lane >> 3) & 1);
    const uint32_t khA = nt * 16;
    const uint32_t khB = rhalf * 16;

    uint32_t qa[4][4];
    {
        const uint32_t rowA = (uint32_t)(w * 16 + rhalf * 8 + (lane & 7)) * 128;
        #pragma unroll
        for (int kc = 0; kc < 4; kc++)
            ldsm4(qa[kc], qsa + rowA + (((uint32_t)(kc * 32) + khA) ^ swl));
    }

    float m0 = -1e30f, m1 = -1e30f, l0 = 0.f, l1 = 0.f;
    float o[8][4];
    #pragma unroll
    for (int nj = 0; nj < 8; nj++)
        #pragma unroll
        for (int r = 0; r < 4; r++) o[nj][r] = 0.f;

    const int c0 = (lane & 3) * 2;

    for (int i = 0; i < NITER; i++) {
        const int bi = i & 1;
        const int j0 = i * 64;
        cp_wait0();
        __syncthreads();
        if (i + 1 < NITER) issue_kv(j0 + 64, bi ^ 1);

        // S = Q K^T  (already scaled via Q)
        float s[8][4];
        #pragma unroll
        for (int nj = 0; nj < 8; nj++)
            #pragma unroll
            for (int r = 0; r < 4; r++) s[nj][r] = 0.f;
        #pragma unroll
        for (int kc = 0; kc < 4; kc++) {
            #pragma unroll
            for (int j = 0; j < 4; j++) {
                uint32_t bb[4];
                const uint32_t row = (uint32_t)((2 * j + nt) * 8 + (lane & 7)) * 128;
                ldsm4(bb, ksa[bi] + row + (((uint32_t)(kc * 32) + khB) ^ swl));
                mma_f16(s[2 * j],     qa[kc], &bb[0]);
                mma_f16(s[2 * j + 1], qa[kc], &bb[2]);
            }
        }

        // mask only needed on the last tile (SEQ = 9*64 + 1)
        if (j0 + 64 > SEQ) {
            #pragma unroll
            for (int nj = 0; nj < 8; nj++) {
                const int col = j0 + nj * 8 + c0;
                if (col >= SEQ)     { s[nj][0] = -1e30f; s[nj][2] = -1e30f; }
                if (col + 1 >= SEQ) { s[nj][1] = -1e30f; s[nj][3] = -1e30f; }
            }
        }

        // online softmax
        float mx0 = -1e30f, mx1 = -1e30f;
        #pragma unroll
        for (int nj = 0; nj < 8; nj++) {
            mx0 = fmaxf(mx0, fmaxf(s[nj][0], s[nj][1]));
            mx1 = fmaxf(mx1, fmaxf(s[nj][2], s[nj][3]));
        }
        mx0 = fmaxf(mx0, __shfl_xor_sync(0xFFFFFFFFu, mx0, 1));
        mx0 = fmaxf(mx0, __shfl_xor_sync(0xFFFFFFFFu, mx0, 2));
        mx1 = fmaxf(mx1, __shfl_xor_sync(0xFFFFFFFFu, mx1, 1));
        mx1 = fmaxf(mx1, __shfl_xor_sync(0xFFFFFFFFu, mx1, 2));
        const float nm0 = fmaxf(m0, mx0), nm1 = fmaxf(m1, mx1);
        const float cr0 = __expf(m0 - nm0), cr1 = __expf(m1 - nm1);
        m0 = nm0; m1 = nm1;
        float rs0 = 0.f, rs1 = 0.f;
        #pragma unroll
        for (int nj = 0; nj < 8; nj++) {
            float p0 = __expf(s[nj][0] - m0);
            float p1 = __expf(s[nj][1] - m0);
            float p2 = __expf(s[nj][2] - m1);
            float p3 = __expf(s[nj][3] - m1);
            s[nj][0] = p0; s[nj][1] = p1; s[nj][2] = p2; s[nj][3] = p3;
            rs0 += p0 + p1;
            rs1 += p2 + p3;
        }
        rs0 += __shfl_xor_sync(0xFFFFFFFFu, rs0, 1);
        rs0 += __shfl_xor_sync(0xFFFFFFFFu, rs0, 2);
        rs1 += __shfl_xor_sync(0xFFFFFFFFu, rs1, 1);
        rs1 += __shfl_xor_sync(0xFFFFFFFFu, rs1, 2);
        l0 = l0 * cr0 + rs0;
        l1 = l1 * cr1 + rs1;
        #pragma unroll
        for (int nj = 0; nj < 8; nj++) {
            o[nj][0] *= cr0; o[nj][1] *= cr0;
            o[nj][2] *= cr1; o[nj][3] *= cr1;
        }

        // O += P V
        #pragma unroll
        for (int kc = 0; kc < 4; kc++) {
            uint32_t pa[4];
            {
                __half2 t0 = __floats2half2_rn(s[2 * kc][0],     s[2 * kc][1]);
                __half2 t1 = __floats2half2_rn(s[2 * kc][2],     s[2 * kc][3]);
                __half2 t2 = __floats2half2_rn(s[2 * kc + 1][0], s[2 * kc + 1][1]);
                __half2 t3 = __floats2half2_rn(s[2 * kc + 1][2], s[2 * kc + 1][3]);
                pa[0] = *(uint32_t*)&t0; pa[1] = *(uint32_t*)&t1;
                pa[2] = *(uint32_t*)&t2; pa[3] = *(uint32_t*)&t3;
            }
            const uint32_t row = (uint32_t)(kc * 16 + rhalf * 8 + (lane & 7)) * 128;
            #pragma unroll
            for (int j = 0; j < 4; j++) {
                uint32_t vb[4];
                const uint32_t colb = 16u * (uint32_t)(2 * j + nt);
                ldsm4t(vb, vsa[bi] + row + (colb ^ swl));
                mma_f16(o[2 * j],     pa, &vb[0]);
                mma_f16(o[2 * j + 1], pa, &vb[2]);
            }
        }
    }

    // epilogue: normalize + fp16 into chunked activation buffer (chunk = head)
    #pragma unroll
    for (int half = 0; half < 2; half++) {
        const int qr = q0 + w * 16 + (lane >> 2) + half * 8;
        if (qr < SEQ) {
            const float inv = 1.0f / (half ? l1 : l0);
            const size_t mtok = (size_t)b * SEQ + qr;
            const uint32_t swr = ((uint32_t)(mtok & 7)) << 4;
            const size_t rowbase = ((size_t)h * MPAD + mtok) * 128;
            #pragma unroll
            for (int nj = 0; nj < 8; nj++) {
                const int d = nj * 8 + c0;
                __half2 h2 = __floats2half2_rn(o[nj][half * 2] * inv,
                                               o[nj][half * 2 + 1] * inv);
                *(uint32_t*)(oa + rowbase + (((uint32_t)(2 * d)) ^ swr)) = *(uint32_t*)&h2;
            }
        }
    }
}

// ---------------------------------------------------------------------------
// Launch
// ---------------------------------------------------------------------------
extern "C" void kernel_launch(void* const* d_in, const int* in_sizes, int n_in,
                              void* d_out, int out_size)
{
    const float* x      = (const float*)d_in[0];
    const float* ln1_g  = (const float*)d_in[1];
    const float* ln1_b  = (const float*)d_in[2];
    const float* w_qkv  = (const float*)d_in[3];
    const float* w_proj = (const float*)d_in[4];
    const float* b_proj = (const float*)d_in[5];
    const float* ln2_g  = (const float*)d_in[6];
    const float* ln2_b  = (const float*)d_in[7];
    const float* w_fc1  = (const float*)d_in[8];
    const float* b_fc1  = (const float*)d_in[9];
    const float* w_fc2  = (const float*)d_in[10];
    const float* b_fc2  = (const float*)d_in[11];
    float* out = (float*)d_out;

    __half *p_qkvh, *p_w; float* p_x1;
    uint8_t *p_actA, *p_actB;
    cudaGetSymbolAddress((void**)&p_qkvh, g_qkvh);
    cudaGetSymbolAddress((void**)&p_x1,   g_x1);
    cudaGetSymbolAddress((void**)&p_actA, g_actA);
    cudaGetSymbolAddress((void**)&p_actB, g_actB);
    cudaGetSymbolAddress((void**)&p_w,    g_w);
    uint8_t* p_wb = (uint8_t*)p_w;

    cudaFuncSetAttribute(gemm_f16_ker<EPI_BIAS_RES>,
                         cudaFuncAttributeMaxDynamicSharedMemorySize, GEMM_SMEM);
    cudaFuncSetAttribute(gemm_f16_ker<EPI_GELU_H>,
                         cudaFuncAttributeMaxDynamicSharedMemorySize, GEMM_SMEM);
    cudaFuncSetAttribute(gemm_f16_ker<EPI_HALF>,
                         cudaFuncAttributeMaxDynamicSharedMemorySize, GEMM_SMEM);

    const int M = MTOK;
    const int MY = (M + 127) / 128;   // 289
    const dim3 blkT(32, 4);

    // 1) LN1 -> fp16 acts A
    ln_f16_ker<<<M, 256>>>(x, ln1_g, ln1_b, p_actA);
    // 2) convert w_qkv
    convT_ker<<<dim3(C_QKV / 32, C_EMB / 32), blkT>>>(w_qkv, p_wb, C_EMB, C_QKV);
    // 3) qkv = h @ w_qkv -> fp16 row-major
    gemm_f16_ker<EPI_HALF><<<dim3(C_QKV / 256, MY), 256, GEMM_SMEM>>>(
        p_actA, p_wb, nullptr, nullptr, nullptr, p_qkvh, nullptr, M, C_QKV, C_EMB);
    // 4) flash attention -> fp16 acts A
    attn_ker<<<dim3(NITER, BATCH * NHEAD), 128>>>(p_qkvh, p_actA);
    // 5) convert w_proj
    convT_ker<<<dim3(C_EMB / 32, C_EMB / 32), blkT>>>(w_proj, p_wb, C_EMB, C_EMB);
    // 6) x1 = x + att @ w_proj + b_proj
    gemm_f16_ker<EPI_BIAS_RES><<<dim3(C_EMB / 256, MY), 256, GEMM_SMEM>>>(
        p_actA, p_wb, b_proj, x, p_x1, nullptr, nullptr, M, C_EMB, C_EMB);
    // 7) LN2 -> fp16 acts A
    ln_f16_ker<<<M, 256>>>(p_x1, ln2_g, ln2_b, p_actA);
    // 8) convert w_fc1
    convT_ker<<<dim3(C_HID / 32, C_EMB / 32), blkT>>>(w_fc1, p_wb, C_EMB, C_HID);
    // 9) ff = gelu(h @ w_fc1 + b_fc1) -> fp16 acts B
    gemm_f16_ker<EPI_GELU_H><<<dim3(C_HID / 256, MY), 256, GEMM_SMEM>>>(
        p_actA, p_wb, b_fc1, nullptr, nullptr, nullptr, p_actB, M, C_HID, C_EMB);
    // 10) convert w_fc2
    convT_ker<<<dim3(C_EMB / 32, C_HID / 32), blkT>>>(w_fc2, p_wb, C_HID, C_EMB);
    // 11) out = x1 + ff @ w_fc2 + b_fc2
    gemm_f16_ker<EPI_BIAS_RES><<<dim3(C_EMB / 256, MY), 256, GEMM_SMEM>>>(
        p_actB, p_wb, b_fc2, p_x1, out, nullptr, nullptr, M, C_EMB, C_HID);
}

// round 9
// speedup vs baseline: 8.0072x; 1.0511x over previous
#include <cuda_runtime.h>
#include <cuda_fp16.h>
#include <math.h>
#include <stdint.h>

// ---------------------------------------------------------------------------
// Problem constants
// ---------------------------------------------------------------------------
#define BATCH   64
#define SEQ     577
#define MTOK    (BATCH * SEQ)      // 36928
#define MPAD    36992              // 289 * 128
#define C_EMB   768
#define C_QKV   2304
#define C_HID   3072
#define NHEAD   12
#define HDIM    64

#define EPI_BIAS_RES  1
#define EPI_GELU_H    2
#define EPI_HALF      3

// ---------------------------------------------------------------------------
// Scratch (device globals)
// ---------------------------------------------------------------------------
__device__ __half g_qkvh[(size_t)MTOK * C_QKV];       // qkv proj, fp16 row-major
__device__ float  g_x1 [(size_t)MTOK * C_EMB];        // residual 1
// fp16 activations, chunked+swizzled: [K/64][MPAD rows][64 fp16 = 128B]
__device__ __half g_actA[(size_t)MPAD * C_EMB];
__device__ __half g_actB[(size_t)MPAD * C_HID];
// fp16 weights, transposed chunked+swizzled: [K/64][N][64 fp16]
__device__ __half g_w   [(size_t)C_HID * C_EMB];

// ---------------------------------------------------------------------------
// PTX helpers
// ---------------------------------------------------------------------------
__device__ __forceinline__ uint32_t cvta_s(const void* p) {
    uint32_t a;
    asm("{ .reg .u64 t; cvta.to.shared.u64 t, %1; cvt.u32.u64 %0, t; }"
        : "=r"(a) : "l"(p));
    return a;
}
__device__ __forceinline__ void mbar_init(uint32_t mbar, uint32_t cnt) {
    asm volatile("mbarrier.init.shared.b64 [%0], %1;" :: "r"(mbar), "r"(cnt) : "memory");
}
__device__ __forceinline__ void mbar_expect_tx(uint32_t mbar, uint32_t bytes) {
    asm volatile("mbarrier.arrive.expect_tx.shared.b64 _, [%0], %1;"
                 :: "r"(mbar), "r"(bytes) : "memory");
}
__device__ __forceinline__ void mbar_arrive(uint32_t mbar) {
    asm volatile("mbarrier.arrive.shared.b64 _, [%0];" :: "r"(mbar) : "memory");
}
__device__ __forceinline__ void mbar_wait(uint32_t mbar, uint32_t phase) {
    asm volatile(
        "{\n\t"
        ".reg .pred P1;\n\t"
        "WAIT_LOOP_%=:\n\t"
        "mbarrier.try_wait.parity.acquire.cta.shared::cta.b64 P1, [%0], %1, 0x989680;\n\t"
        "@P1 bra.uni WAIT_DONE_%=;\n\t"
        "bra.uni WAIT_LOOP_%=;\n\t"
        "WAIT_DONE_%=:\n\t"
        "}"
        :: "r"(mbar), "r"(phase) : "memory");
}
__device__ __forceinline__ void bulk_ldg(uint32_t dst, const void* src,
                                         uint32_t bytes, uint32_t mbar) {
    asm volatile(
        "cp.async.bulk.shared::cluster.global.mbarrier::complete_tx::bytes "
        "[%0], [%1], %2, [%3];"
        :: "r"(dst), "l"(src), "r"(bytes), "r"(mbar) : "memory");
}
__device__ __forceinline__ void cp16(uint32_t dst, const void* src, uint32_t srcsize) {
    asm volatile("cp.async.cg.shared.global [%0], [%1], 16, %2;"
                 :: "r"(dst), "l"(src), "r"(srcsize) : "memory");
}
__device__ __forceinline__ void cp_commit() {
    asm volatile("cp.async.commit_group;" ::: "memory");
}
__device__ __forceinline__ void cp_wait0() {
    asm volatile("cp.async.wait_group 0;" ::: "memory");
}
__device__ __forceinline__ void ldsm4(uint32_t* r, uint32_t addr) {
    asm volatile("ldmatrix.sync.aligned.m8n8.x4.shared.b16 {%0,%1,%2,%3}, [%4];"
                 : "=r"(r[0]), "=r"(r[1]), "=r"(r[2]), "=r"(r[3]) : "r"(addr));
}
__device__ __forceinline__ void ldsm4t(uint32_t* r, uint32_t addr) {
    asm volatile("ldmatrix.sync.aligned.m8n8.x4.trans.shared.b16 {%0,%1,%2,%3}, [%4];"
                 : "=r"(r[0]), "=r"(r[1]), "=r"(r[2]), "=r"(r[3]) : "r"(addr));
}
__device__ __forceinline__ void mma_f16(float* c, const uint32_t* a, const uint32_t* b) {
    asm volatile(
        "mma.sync.aligned.m16n8k16.row.col.f32.f16.f16.f32 "
        "{%0,%1,%2,%3},{%4,%5,%6,%7},{%8,%9},{%0,%1,%2,%3};"
        : "+f"(c[0]), "+f"(c[1]), "+f"(c[2]), "+f"(c[3])
        : "r"(a[0]), "r"(a[1]), "r"(a[2]), "r"(a[3]), "r"(b[0]), "r"(b[1]));
}

// ---------------------------------------------------------------------------
// Fused LayerNorm + fp16 convert: warp-per-row, 8 rows per block.
// MTOK = 36928 = 8 * 4616 exactly.
// ---------------------------------------------------------------------------
__global__ __launch_bounds__(256) void ln_f16_ker(const float* __restrict__ x,
                                                  const float* __restrict__ gamma,
                                                  const float* __restrict__ beta,
                                                  uint8_t* __restrict__ dst)
{
    const int lane = threadIdx.x & 31, w = threadIdx.x >> 5;
    const int row = blockIdx.x * 8 + w;
    const float* xr = x + (size_t)row * C_EMB;

    float v[24];
    float s = 0.f, s2 = 0.f;
    #pragma unroll
    for (int g = 0; g < 3; g++) {
        const float4* p = (const float4*)(xr + g * 256 + lane * 8);
        float4 a = p[0], b = p[1];
        v[g*8+0]=a.x; v[g*8+1]=a.y; v[g*8+2]=a.z; v[g*8+3]=a.w;
        v[g*8+4]=b.x; v[g*8+5]=b.y; v[g*8+6]=b.z; v[g*8+7]=b.w;
        #pragma unroll
        for (int i = 0; i < 8; i++) { s += v[g*8+i]; s2 += v[g*8+i]*v[g*8+i]; }
    }
    #pragma unroll
    for (int off = 16; off > 0; off >>= 1) {
        s  += __shfl_xor_sync(0xFFFFFFFFu, s,  off);
        s2 += __shfl_xor_sync(0xFFFFFFFFu, s2, off);
    }
    const float mean = s * (1.0f / C_EMB);
    const float rstd = rsqrtf(s2 * (1.0f / C_EMB) - mean * mean + 1e-5f);

    #pragma unroll
    for (int g = 0; g < 3; g++) {
        const int k = g * 256 + lane * 8;
        const float4* gp = (const float4*)(gamma + k);
        const float4* bp = (const float4*)(beta + k);
        float4 g0 = gp[0], g1 = gp[1], b0 = bp[0], b1 = bp[1];
        float gg[8] = {g0.x,g0.y,g0.z,g0.w,g1.x,g1.y,g1.z,g1.w};
        float bb[8] = {b0.x,b0.y,b0.z,b0.w,b1.x,b1.y,b1.z,b1.w};
        union { __half h[8]; uint4 u; } uo;
        #pragma unroll
        for (int i = 0; i < 8; i++)
            uo.h[i] = __float2half_rn((v[g*8+i] - mean) * rstd * gg[i] + bb[i]);
        size_t base = ((size_t)(k >> 6) * MPAD + row) * 128
                    + ((uint32_t)((k & 63) * 2) ^ (uint32_t)((row & 7) << 4));
        *(uint4*)(dst + base) = uo.u;
    }
}

// ---------------------------------------------------------------------------
// convT: fp32 weights [K,N] -> transposed fp16 chunked swizzled [K/64][N][64]
// ---------------------------------------------------------------------------
__global__ void convT_ker(const float* __restrict__ w,
                          uint8_t* __restrict__ dst, int K, int N)
{
    __shared__ float tile[32][33];
    const int n0 = blockIdx.x * 32, k0 = blockIdx.y * 32;
    const int tx = threadIdx.x, ty = threadIdx.y;
    for (int i = ty; i < 32; i += 4)
        tile[i][tx] = w[(size_t)(k0 + i) * N + n0 + tx];
    __syncthreads();
    const int n = n0 + tx;
    const int k = k0 + ty * 8;
    union { __half h[8]; uint4 u; } uo;
    #pragma unroll
    for (int i = 0; i < 8; i++)
        uo.h[i] = __float2half_rn(tile[ty * 8 + i][tx]);
    size_t base = ((size_t)(k >> 6) * N + n) * 128
                + ((uint32_t)((k & 63) * 2) ^ (uint32_t)((n & 7) << 4));
    *(uint4*)(dst + base) = uo.u;
}

// ---------------------------------------------------------------------------
// fp16 warp-MMA GEMM: BM=128, BN=256, BK=64, 4-stage pipeline,
// warp-specialized producer (warp 8) + 8 compute warps. 288 threads.
// ---------------------------------------------------------------------------
#define NSTAGE      4
#define STAGE_BYTES 49152     // A 16K | B 32K
#define GEMM_SMEM   (NSTAGE * STAGE_BYTES + 1024)
#define GTHREADS    288

template<int EPI>
__global__ __launch_bounds__(GTHREADS, 1) void gemm_f16_ker(
    const uint8_t* __restrict__ A, const uint8_t* __restrict__ B,
    const float* __restrict__ bias, const float* __restrict__ res,
    float* __restrict__ C, __half* __restrict__ Ch, uint8_t* __restrict__ Sx,
    int M, int N, int K)
{
    extern __shared__ uint8_t dynsmem[];
    __shared__ __align__(8) uint64_t s_bar[2 * NSTAGE];

    const int t = threadIdx.x, lane = t & 31, wid = t >> 5;
    const int bm = blockIdx.y * 128, bn = blockIdx.x * 256;

    const uint32_t sbase = (cvta_s(dynsmem) + 1023u) & ~1023u;
    uint32_t bfull[NSTAGE], bempty[NSTAGE];
    #pragma unroll
    for (int s = 0; s < NSTAGE; s++) {
        bfull[s]  = cvta_s(&s_bar[s]);
        bempty[s] = cvta_s(&s_bar[NSTAGE + s]);
    }
    if (t == 0) {
        #pragma unroll
        for (int s = 0; s < NSTAGE; s++) {
            mbar_init(bfull[s], 1);
            mbar_init(bempty[s], 8);
        }
    }
    __syncthreads();

    const int nc = K >> 6;

    // ---- producer warp ----
    if (wid == 8) {
        if (lane == 0) {
            int eph[NSTAGE];
            #pragma unroll
            for (int s = 0; s < NSTAGE; s++) eph[s] = 0;
            for (int c = 0; c < nc; c++) {
                const int s = c % NSTAGE;
                if (c >= NSTAGE) { mbar_wait(bempty[s], eph[s]); eph[s] ^= 1; }
                const uint32_t sb = sbase + (uint32_t)s * STAGE_BYTES;
                mbar_expect_tx(bfull[s], STAGE_BYTES);
                bulk_ldg(sb,         A + ((size_t)c * MPAD + bm) * 128, 16384, bfull[s]);
                bulk_ldg(sb + 16384, B + ((size_t)c * N + bn) * 128,    32768, bfull[s]);
            }
        }
        return;
    }

    // ---- compute warps (0..7) ----
    const int wm = wid >> 1, wn = wid & 1;
    const uint32_t sw = (uint32_t)(lane & 7) << 4;
    uint32_t rta[2], rtb[8];
    {
        const int rowoff = ((lane >> 3) & 1) * 8 + (lane & 7);
        rta[0] = (uint32_t)(wm * 32 +  0 + rowoff) * 128;
        rta[1] = (uint32_t)(wm * 32 + 16 + rowoff) * 128;
        const int nt = lane >> 4;
        #pragma unroll
        for (int j = 0; j < 8; j++)
            rtb[j] = (uint32_t)(wn * 128 + (2 * j + nt) * 8 + (lane & 7)) * 128 + 16384;
    }
    const uint32_t khA16 = (uint32_t)(lane >> 4) * 16;
    const uint32_t khB16 = (uint32_t)((lane >> 3) & 1) * 16;

    float acc[2][16][4];
    #pragma unroll
    for (int mi = 0; mi < 2; mi++)
        #pragma unroll
        for (int ni = 0; ni < 16; ni++)
            #pragma unroll
            for (int r = 0; r < 4; r++) acc[mi][ni][r] = 0.f;

    int fph[NSTAGE];
    #pragma unroll
    for (int s = 0; s < NSTAGE; s++) fph[s] = 0;

    for (int c = 0; c < nc; c++) {
        const int s = c % NSTAGE;
        mbar_wait(bfull[s], fph[s]); fph[s] ^= 1;
        const uint32_t sb = sbase + (uint32_t)s * STAGE_BYTES;
        #pragma unroll
        for (int ks = 0; ks < 4; ks++) {
            const uint32_t offA = (uint32_t)(ks * 32 + khA16) ^ sw;
            const uint32_t offB = (uint32_t)(ks * 32 + khB16) ^ sw;
            uint32_t a[2][4];
            ldsm4(a[0], sb + rta[0] + offA);
            ldsm4(a[1], sb + rta[1] + offA);
            #pragma unroll
            for (int j = 0; j < 8; j++) {
                uint32_t b[4];
                ldsm4(b, sb + rtb[j] + offB);
                mma_f16(acc[0][2 * j],     a[0], &b[0]);
                mma_f16(acc[0][2 * j + 1], a[0], &b[2]);
                mma_f16(acc[1][2 * j],     a[1], &b[0]);
                mma_f16(acc[1][2 * j + 1], a[1], &b[2]);
            }
        }
        if (lane == 0) mbar_arrive(bempty[s]);
    }

    // epilogue
    const int row0 = bm + wm * 32 + (lane >> 2);
    const int col0 = bn + wn * 128 + (lane & 3) * 2;
    #pragma unroll
    for (int mi = 0; mi < 2; mi++) {
        #pragma unroll
        for (int ni = 0; ni < 16; ni++) {
            const int col = col0 + ni * 8;
            float bb0 = 0.f, bb1 = 0.f;
            if (EPI != EPI_HALF) { bb0 = bias[col]; bb1 = bias[col + 1]; }
            #pragma unroll
            for (int half = 0; half < 2; half++) {
                const int row = row0 + mi * 16 + half * 8;
                if (row < M) {
                    float v0 = acc[mi][ni][half * 2]     + bb0;
                    float v1 = acc[mi][ni][half * 2 + 1] + bb1;
                    if (EPI == EPI_HALF) {
                        __half2 h2 = __floats2half2_rn(acc[mi][ni][half * 2],
                                                       acc[mi][ni][half * 2 + 1]);
                        *(uint32_t*)(Ch + (size_t)row * N + col) = *(uint32_t*)&h2;
                    } else if (EPI == EPI_GELU_H) {
                        v0 = 0.5f * v0 * (1.0f + erff(v0 * 0.70710678118654752f));
                        v1 = 0.5f * v1 * (1.0f + erff(v1 * 0.70710678118654752f));
                        __half2 h2 = __floats2half2_rn(v0, v1);
                        size_t base = ((size_t)(col >> 6) * MPAD + row) * 128
                                    + ((uint32_t)(2 * (col & 63)) ^ (uint32_t)((row & 7) << 4));
                        *(uint32_t*)(Sx + base) = *(uint32_t*)&h2;
                    } else { // EPI_BIAS_RES
                        const float2 r2 = *(const float2*)(res + (size_t)row * N + col);
                        *(float2*)(C + (size_t)row * N + col) =
                            make_float2(v0 + r2.x, v1 + r2.y);
                    }
                }
            }
        }
    }
}

// ---------------------------------------------------------------------------
// fp16 flash attention: KV tile 128, exp2 softmax (log2e folded into Q scale).
// grid (10, B*H), 128 threads, double-buffered cp.async K/V, dynamic smem.
// smem: Q 8K | K 2x16K | V 2x16K = 72K
// ---------------------------------------------------------------------------
#define NITER2 ((SEQ + 127) / 128)   // 5
#define ATTN_SMEM (8192 + 4 * 16384)

__global__ __launch_bounds__(128) void attn_ker(const __half* __restrict__ qkv,
                                                uint8_t* __restrict__ oa)
{
    extern __shared__ uint8_t sm[];
    const uint32_t qsa = cvta_s(sm);
    const uint32_t ksa[2] = { qsa + 8192,  qsa + 8192 + 16384 };
    const uint32_t vsa[2] = { qsa + 40960, qsa + 40960 + 16384 };

    const int bh = blockIdx.y;
    const int b  = bh / NHEAD;
    const int h  = bh % NHEAD;
    const int q0 = blockIdx.x * 64;
    const int t  = threadIdx.x, lane = t & 31, w = t >> 5;

    auto issue_kv = [&](int j0, int bi) {
        for (int idx = t; idx < 1024; idx += 128) {
            const int r = idx >> 3, g = idx & 7;
            const int kr = j0 + r;
            const int krc = kr < SEQ ? kr : SEQ - 1;
            const uint32_t sz = kr < SEQ ? 16u : 0u;
            const __half* src = qkv + (size_t)(b * SEQ + krc) * C_QKV + h * HDIM + g * 8;
            const uint32_t off = r * 128 + ((g * 16) ^ ((r & 7) << 4));
            cp16(ksa[bi] + off, src + C_EMB,     sz);
            cp16(vsa[bi] + off, src + 2 * C_EMB, sz);
        }
        cp_commit();
    };

    issue_kv(0, 0);

    // load Q, pre-scaled by 0.125 * log2(e) -> S is in log2 units
    const __half2 qsc = __floats2half2_rn(0.18033688f, 0.18033688f);
    for (int idx = t; idx < 1024; idx += 128) {
        const int r = idx >> 4, g = idx & 15;
        const int qr = q0 + r;
        uint2 val = make_uint2(0u, 0u);
        if (qr < SEQ) {
            val = *(const uint2*)(qkv + (size_t)(b * SEQ + qr) * C_QKV + h * HDIM + g * 4);
            __half2* hp = (__half2*)&val;
            hp[0] = __hmul2(hp[0], qsc);
            hp[1] = __hmul2(hp[1], qsc);
        }
        *(uint2*)(sm + r * 128 + ((g * 8) ^ ((r & 7) << 4))) = val;
    }
    __syncthreads();

    const uint32_t swl = (uint32_t)(lane & 7) << 4;
    const uint32_t nt  = (uint32_t)(lane >> 4);
    const uint32_t rhalf = (uint32_t)((lane >> 3) & 1);
    const uint32_t khA = nt * 16;
    const uint32_t khB = rhalf * 16;

    uint32_t qa[4][4];
    {
        const uint32_t rowA = (uint32_t)(w * 16 + rhalf * 8 + (lane & 7)) * 128;
        #pragma unroll
        for (int kc = 0; kc < 4; kc++)
            ldsm4(qa[kc], qsa + rowA + (((uint32_t)(kc * 32) + khA) ^ swl));
    }

    float m0 = -1e30f, m1 = -1e30f, l0 = 0.f, l1 = 0.f;
    float o[8][4];
    #pragma unroll
    for (int nj = 0; nj < 8; nj++)
        #pragma unroll
        for (int r = 0; r < 4; r++) o[nj][r] = 0.f;

    const int c0 = (lane & 3) * 2;

    for (int i = 0; i < NITER2; i++) {
        const int bi = i & 1;
        const int j0 = i * 128;
        cp_wait0();
        __syncthreads();
        if (i + 1 < NITER2) issue_kv(j0 + 128, bi ^ 1);

        // S = Q K^T (log2 units)
        float s[16][4];
        #pragma unroll
        for (int nj = 0; nj < 16; nj++)
            #pragma unroll
            for (int r = 0; r < 4; r++) s[nj][r] = 0.f;
        #pragma unroll
        for (int kc = 0; kc < 4; kc++) {
            #pragma unroll
            for (int j = 0; j < 8; j++) {
                uint32_t bb[4];
                const uint32_t row = (uint32_t)((2 * j + nt) * 8 + (lane & 7)) * 128;
                ldsm4(bb, ksa[bi] + row + (((uint32_t)(kc * 32) + khB) ^ swl));
                mma_f16(s[2 * j],     qa[kc], &bb[0]);
                mma_f16(s[2 * j + 1], qa[kc], &bb[2]);
            }
        }

        // mask only on the last tile (SEQ = 4*128 + 65)
        if (j0 + 128 > SEQ) {
            #pragma unroll
            for (int nj = 0; nj < 16; nj++) {
                const int col = j0 + nj * 8 + c0;
                if (col >= SEQ)     { s[nj][0] = -1e30f; s[nj][2] = -1e30f; }
                if (col + 1 >= SEQ) { s[nj][1] = -1e30f; s[nj][3] = -1e30f; }
            }
        }

        // online softmax (base-2)
        float mx0 = -1e30f, mx1 = -1e30f;
        #pragma unroll
        for (int nj = 0; nj < 16; nj++) {
            mx0 = fmaxf(mx0, fmaxf(s[nj][0], s[nj][1]));
            mx1 = fmaxf(mx1, fmaxf(s[nj][2], s[nj][3]));
        }
        mx0 = fmaxf(mx0, __shfl_xor_sync(0xFFFFFFFFu, mx0, 1));
        mx0 = fmaxf(mx0, __shfl_xor_sync(0xFFFFFFFFu, mx0, 2));
        mx1 = fmaxf(mx1, __shfl_xor_sync(0xFFFFFFFFu, mx1, 1));
        mx1 = fmaxf(mx1, __shfl_xor_sync(0xFFFFFFFFu, mx1, 2));
        const float nm0 = fmaxf(m0, mx0), nm1 = fmaxf(m1, mx1);
        const float cr0 = exp2f(m0 - nm0), cr1 = exp2f(m1 - nm1);
        m0 = nm0; m1 = nm1;
        float rs0 = 0.f, rs1 = 0.f;
        #pragma unroll
        for (int nj = 0; nj < 16; nj++) {
            float p0 = exp2f(s[nj][0] - m0);
            float p1 = exp2f(s[nj][1] - m0);
            float p2 = exp2f(s[nj][2] - m1);
            float p3 = exp2f(s[nj][3] - m1);
            s[nj][0] = p0; s[nj][1] = p1; s[nj][2] = p2; s[nj][3] = p3;
            rs0 += p0 + p1;
            rs1 += p2 + p3;
        }
        rs0 += __shfl_xor_sync(0xFFFFFFFFu, rs0, 1);
        rs0 += __shfl_xor_sync(0xFFFFFFFFu, rs0, 2);
        rs1 += __shfl_xor_sync(0xFFFFFFFFu, rs1, 1);
        rs1 += __shfl_xor_sync(0xFFFFFFFFu, rs1, 2);
        l0 = l0 * cr0 + rs0;
        l1 = l1 * cr1 + rs1;
        #pragma unroll
        for (int nj = 0; nj < 8; nj++) {
            o[nj][0] *= cr0; o[nj][1] *= cr0;
            o[nj][2] *= cr1; o[nj][3] *= cr1;
        }

        // O += P V
        #pragma unroll
        for (int kc = 0; kc < 8; kc++) {
            uint32_t pa[4];
            {
                __half2 t0 = __floats2half2_rn(s[2 * kc][0],     s[2 * kc][1]);
                __half2 t1 = __floats2half2_rn(s[2 * kc][2],     s[2 * kc][3]);
                __half2 t2 = __floats2half2_rn(s[2 * kc + 1][0], s[2 * kc + 1][1]);
                __half2 t3 = __floats2half2_rn(s[2 * kc + 1][2], s[2 * kc + 1][3]);
                pa[0] = *(uint32_t*)&t0; pa[1] = *(uint32_t*)&t1;
                pa[2] = *(uint32_t*)&t2; pa[3] = *(uint32_t*)&t3;
            }
            const uint32_t row = (uint32_t)(kc * 16 + rhalf * 8 + (lane & 7)) * 128;
            #pragma unroll
            for (int j = 0; j < 4; j++) {
                uint32_t vb[4];
                const uint32_t colb = 16u * (uint32_t)(2 * j + nt);
                ldsm4t(vb, vsa[bi] + row + (colb ^ swl));
                mma_f16(o[2 * j],     pa, &vb[0]);
                mma_f16(o[2 * j + 1], pa, &vb[2]);
            }
        }
    }

    // epilogue
    #pragma unroll
    for (int half = 0; half < 2; half++) {
        const int qr = q0 + w * 16 + (lane >> 2) + half * 8;
        if (qr < SEQ) {
            const float inv = 1.0f / (half ? l1 : l0);
            const size_t mtok = (size_t)b * SEQ + qr;
            const uint32_t swr = ((uint32_t)(mtok & 7)) << 4;
            const size_t rowbase = ((size_t)h * MPAD + mtok) * 128;
            #pragma unroll
            for (int nj = 0; nj < 8; nj++) {
                const int d = nj * 8 + c0;
                __half2 h2 = __floats2half2_rn(o[nj][half * 2] * inv,
                                               o[nj][half * 2 + 1] * inv);
                *(uint32_t*)(oa + rowbase + (((uint32_t)(2 * d)) ^ swr)) = *(uint32_t*)&h2;
            }
        }
    }
}

// ---------------------------------------------------------------------------
// Launch
// ---------------------------------------------------------------------------
extern "C" void kernel_launch(void* const* d_in, const int* in_sizes, int n_in,
                              void* d_out, int out_size)
{
    const float* x      = (const float*)d_in[0];
    const float* ln1_g  = (const float*)d_in[1];
    const float* ln1_b  = (const float*)d_in[2];
    const float* w_qkv  = (const float*)d_in[3];
    const float* w_proj = (const float*)d_in[4];
    const float* b_proj = (const float*)d_in[5];
    const float* ln2_g  = (const float*)d_in[6];
    const float* ln2_b  = (const float*)d_in[7];
    const float* w_fc1  = (const float*)d_in[8];
    const float* b_fc1  = (const float*)d_in[9];
    const float* w_fc2  = (const float*)d_in[10];
    const float* b_fc2  = (const float*)d_in[11];
    float* out = (float*)d_out;

    __half *p_qkvh, *p_w; float* p_x1;
    uint8_t *p_actA, *p_actB;
    cudaGetSymbolAddress((void**)&p_qkvh, g_qkvh);
    cudaGetSymbolAddress((void**)&p_x1,   g_x1);
    cudaGetSymbolAddress((void**)&p_actA, g_actA);
    cudaGetSymbolAddress((void**)&p_actB, g_actB);
    cudaGetSymbolAddress((void**)&p_w,    g_w);
    uint8_t* p_wb = (uint8_t*)p_w;

    cudaFuncSetAttribute(gemm_f16_ker<EPI_BIAS_RES>,
                         cudaFuncAttributeMaxDynamicSharedMemorySize, GEMM_SMEM);
    cudaFuncSetAttribute(gemm_f16_ker<EPI_GELU_H>,
                         cudaFuncAttributeMaxDynamicSharedMemorySize, GEMM_SMEM);
    cudaFuncSetAttribute(gemm_f16_ker<EPI_HALF>,
                         cudaFuncAttributeMaxDynamicSharedMemorySize, GEMM_SMEM);
    cudaFuncSetAttribute(attn_ker,
                         cudaFuncAttributeMaxDynamicSharedMemorySize, ATTN_SMEM);

    const int M = MTOK;
    const int MY = (M + 127) / 128;   // 289
    const dim3 blkT(32, 4);

    // 1) LN1 -> fp16 acts A
    ln_f16_ker<<<MTOK / 8, 256>>>(x, ln1_g, ln1_b, p_actA);
    // 2) convert w_qkv
    convT_ker<<<dim3(C_QKV / 32, C_EMB / 32), blkT>>>(w_qkv, p_wb, C_EMB, C_QKV);
    // 3) qkv = h @ w_qkv -> fp16 row-major
    gemm_f16_ker<EPI_HALF><<<dim3(C_QKV / 256, MY), GTHREADS, GEMM_SMEM>>>(
        p_actA, p_wb, nullptr, nullptr, nullptr, p_qkvh, nullptr, M, C_QKV, C_EMB);
    // 4) flash attention -> fp16 acts A
    attn_ker<<<dim3((SEQ + 63) / 64, BATCH * NHEAD), 128, ATTN_SMEM>>>(p_qkvh, p_actA);
    // 5) convert w_proj
    convT_ker<<<dim3(C_EMB / 32, C_EMB / 32), blkT>>>(w_proj, p_wb, C_EMB, C_EMB);
    // 6) x1 = x + att @ w_proj + b_proj
    gemm_f16_ker<EPI_BIAS_RES><<<dim3(C_EMB / 256, MY), GTHREADS, GEMM_SMEM>>>(
        p_actA, p_wb, b_proj, x, p_x1, nullptr, nullptr, M, C_EMB, C_EMB);
    // 7) LN2 -> fp16 acts A
    ln_f16_ker<<<MTOK / 8, 256>>>(p_x1, ln2_g, ln2_b, p_actA);
    // 8) convert w_fc1
    convT_ker<<<dim3(C_HID / 32, C_EMB / 32), blkT>>>(w_fc1, p_wb, C_EMB, C_HID);
    // 9) ff = gelu(h @ w_fc1 + b_fc1) -> fp16 acts B
    gemm_f16_ker<EPI_GELU_H><<<dim3(C_HID / 256, MY), GTHREADS, GEMM_SMEM>>>(
        p_actA, p_wb, b_fc1, nullptr, nullptr, nullptr, p_actB, M, C_HID, C_EMB);
    // 10) convert w_fc2
    convT_ker<<<dim3(C_EMB / 32, C_HID / 32), blkT>>>(w_fc2, p_wb, C_HID, C_EMB);
    // 11) out = x1 + ff @ w_fc2 + b_fc2
    gemm_f16_ker<EPI_BIAS_RES><<<dim3(C_EMB / 256, MY), GTHREADS, GEMM_SMEM>>>(
        p_actB, p_wb, b_fc2, p_x1, out, nullptr, nullptr, M, C_EMB, C_HID);
}